// round 2
// baseline (speedup 1.0000x reference)
#include <cuda_runtime.h>
#include <math.h>
#include <stdio.h>

#define T_LEN 2048
#define B_SZ  32
#define DM    512
#define NH    8
#define DH    64
#define DFF   2048
#define NC    64
#define EV    256
#define DPE   256
#define NL    2
#define CHK   64
#define NCH   (T_LEN / CHK)          // 32
#define MROWS (T_LEN * B_SZ)         // 65536
#define EPS_ATTN 1e-6f
#define EPS_LN   1e-5f

// ---------------- scratch (device globals; no allocations allowed) ----------------
__device__ float g_h[MROWS * DM];        // 134 MB
__device__ float g_q[MROWS * DM];
__device__ float g_k[MROWS * DM];
__device__ float g_v[MROWS * DM];
__device__ float g_attn[MROWS * DM];
__device__ float g_ff[MROWS * DFF];      // 537 MB
__device__ float g_S[(size_t)B_SZ * NH * NCH * DH * DH];  // per-chunk KtV sums -> exclusive prefix
__device__ float g_Z[(size_t)B_SZ * NH * NCH * DH];

// ---------------- embedding + positional encoding ----------------
__global__ void embed_kernel(const int* __restrict__ x, const float* __restrict__ E) {
    int idx = blockIdx.x * blockDim.x + threadIdx.x;   // over MROWS*DM
    int d  = idx & (DM - 1);
    int tb = idx >> 9;          // /DM
    int b  = tb & (B_SZ - 1);
    int t  = tb >> 5;           // /B_SZ
    float val;
    if (d < EV) {
        val = E[(size_t)x[t * B_SZ + b] * EV + d];
    } else {
        int j = d - EV;
        // match float32 reference arithmetic: freq = exp(float(2*(j/2)) * float(-ln(10000)/256))
        float freq = expf((float)(j & ~1) * (-9.210340371976184f / 256.0f));
        float ang = (float)t * freq;
        val = (j & 1) ? cosf(ang) : sinf(ang);
    }
    g_h[idx] = val;
}

// ---------------- generic tiled fp32 GEMM: C = act(A[M,K] @ W[K,N] + bias) ----------------
// ACT: 0 none, 1 phi(u)=elu(u)+1, 2 relu.  OUTMODE: 0 row-major C, 1 out[b][t][n] with row=(t,b)
template<int ACT, int OUTMODE>
__global__ void __launch_bounds__(256)
gemm_kernel(const float* __restrict__ A, const float* __restrict__ W,
            const float* __restrict__ bias, float* __restrict__ C,
            int M, int N, int K)
{
    __shared__ float As[16][68];   // [k][m], padded
    __shared__ float Bs[16][64];   // [k][n]

    int tid = threadIdx.x;
    int bn = blockIdx.x * 64;
    int bm = blockIdx.y * 64;
    int tx = tid & 15, ty = tid >> 4;

    int arow = tid >> 2;              // 0..63
    int acol = (tid & 3) << 2;        // 0,4,8,12
    int brow = tid >> 4;              // 0..15
    int bcol = (tid & 15) << 2;       // 0..60

    const float* Ap = A + (size_t)(bm + arow) * K + acol;
    const float* Wp = W + (size_t)brow * N + bn + bcol;

    float acc[4][4] = {};

    for (int k0 = 0; k0 < K; k0 += 16) {
        float4 av = *(const float4*)Ap;  Ap += 16;
        float4 bv = *(const float4*)Wp;  Wp += (size_t)16 * N;
        As[acol + 0][arow] = av.x;
        As[acol + 1][arow] = av.y;
        As[acol + 2][arow] = av.z;
        As[acol + 3][arow] = av.w;
        *(float4*)&Bs[brow][bcol] = bv;
        __syncthreads();
        #pragma unroll
        for (int kk = 0; kk < 16; kk++) {
            float4 a4 = *(const float4*)&As[kk][ty << 2];
            float4 b4 = *(const float4*)&Bs[kk][tx << 2];
            float a[4] = {a4.x, a4.y, a4.z, a4.w};
            float b[4] = {b4.x, b4.y, b4.z, b4.w};
            #pragma unroll
            for (int i = 0; i < 4; i++)
                #pragma unroll
                for (int j = 0; j < 4; j++)
                    acc[i][j] += a[i] * b[j];
        }
        __syncthreads();
    }

    #pragma unroll
    for (int i = 0; i < 4; i++) {
        int row = bm + (ty << 2) + i;
        #pragma unroll
        for (int j = 0; j < 4; j++) {
            int col = bn + (tx << 2) + j;
            float val = acc[i][j] + bias[col];
            if (ACT == 1) val = (val > 0.f) ? (val + 1.f) : expf(val);   // elu+1
            if (ACT == 2) val = fmaxf(val, 0.f);
            if (OUTMODE == 0) {
                C[(size_t)row * N + col] = val;
            } else {
                int t = row >> 5, b = row & 31;     // row = t*B + b
                C[((size_t)b * T_LEN + t) * NC + col] = val;
            }
        }
    }
}

// ---------------- residual add + LayerNorm (in place on h) ----------------
__global__ void __launch_bounds__(128)
ln_kernel(float* __restrict__ h, const float* __restrict__ addv,
          const float* __restrict__ g, const float* __restrict__ be)
{
    int row = blockIdx.x, tid = threadIdx.x;
    size_t base = (size_t)row * DM + (tid << 2);
    float4 hv = *(const float4*)&h[base];
    float4 av = *(const float4*)&addv[base];
    float x0 = hv.x + av.x, x1 = hv.y + av.y, x2 = hv.z + av.z, x3 = hv.w + av.w;

    __shared__ float red[4];
    int wid = tid >> 5, lane = tid & 31;

    float s = x0 + x1 + x2 + x3;
    #pragma unroll
    for (int o = 16; o > 0; o >>= 1) s += __shfl_xor_sync(0xffffffffu, s, o);
    if (lane == 0) red[wid] = s;
    __syncthreads();
    float mean = (red[0] + red[1] + red[2] + red[3]) * (1.0f / DM);

    float d0 = x0 - mean, d1 = x1 - mean, d2 = x2 - mean, d3 = x3 - mean;
    float vs = d0 * d0 + d1 * d1 + d2 * d2 + d3 * d3;
    #pragma unroll
    for (int o = 16; o > 0; o >>= 1) vs += __shfl_xor_sync(0xffffffffu, vs, o);
    __syncthreads();
    if (lane == 0) red[wid] = vs;
    __syncthreads();
    float var = (red[0] + red[1] + red[2] + red[3]) * (1.0f / DM);
    float inv = 1.0f / sqrtf(var + EPS_LN);

    int d = tid << 2;
    float4 gv = *(const float4*)&g[d];
    float4 bv = *(const float4*)&be[d];
    float4 o;
    o.x = d0 * inv * gv.x + bv.x;
    o.y = d1 * inv * gv.y + bv.y;
    o.z = d2 * inv * gv.z + bv.z;
    o.w = d3 * inv * gv.w + bv.w;
    *(float4*)&h[base] = o;
}

// ---------------- attention pass A: per-chunk KtV sums and K column sums ----------------
__global__ void __launch_bounds__(256)
chunk_sums_kernel(const float* __restrict__ K_, const float* __restrict__ V_)
{
    int blk = blockIdx.x;
    int c = blk % NCH, bh = blk / NCH;
    int b = bh >> 3, hh = bh & 7;

    __shared__ float ks[CHK * DH];
    __shared__ float vsm[CHK * DH];
    int tid = threadIdx.x;
    for (int idx = tid * 4; idx < CHK * DH; idx += 256 * 4) {
        int t = idx >> 6, d = idx & 63;
        size_t gidx = ((size_t)(c * CHK + t) * B_SZ + b) * DM + hh * DH + d;
        *(float4*)&ks[idx]  = *(const float4*)&K_[gidx];
        *(float4*)&vsm[idx] = *(const float4*)&V_[gidx];
    }
    __syncthreads();

    int d  = tid >> 2;
    int mb = (tid & 3) << 4;
    float acc[16] = {};
    float zacc = 0.f;
    for (int t = 0; t < CHK; t++) {
        float kd = ks[t * DH + d];
        zacc += kd;
        const float* vp = &vsm[t * DH + mb];
        #pragma unroll
        for (int m = 0; m < 16; m += 4) {
            float4 vv = *(const float4*)&vp[m];
            acc[m + 0] += kd * vv.x;
            acc[m + 1] += kd * vv.y;
            acc[m + 2] += kd * vv.z;
            acc[m + 3] += kd * vv.w;
        }
    }
    size_t sbase = ((size_t)bh * NCH + c) * (DH * DH) + d * DH + mb;
    #pragma unroll
    for (int m = 0; m < 16; m += 4) {
        float4 o = {acc[m], acc[m + 1], acc[m + 2], acc[m + 3]};
        *(float4*)&g_S[sbase + m] = o;
    }
    if ((tid & 3) == 0) g_Z[((size_t)bh * NCH + c) * DH + d] = zacc;
}

// ---------------- exclusive prefix over chunks (per b,h) ----------------
__global__ void __launch_bounds__(256)
prefix_kernel()
{
    int bh = blockIdx.x;
    int tid = threadIdx.x;
    float run[16] = {};
    for (int c = 0; c < NCH; c++) {
        size_t base = ((size_t)bh * NCH + c) * (DH * DH) + tid * 16;
        #pragma unroll
        for (int e = 0; e < 16; e++) {
            float t = g_S[base + e];
            g_S[base + e] = run[e];
            run[e] += t;
        }
    }
    if (tid < DH) {
        float rz = 0.f;
        for (int c = 0; c < NCH; c++) {
            size_t zi = ((size_t)bh * NCH + c) * DH + tid;
            float t = g_Z[zi];
            g_Z[zi] = rz;
            rz += t;
        }
    }
}

// ---------------- attention pass B: per-chunk causal output ----------------
// out_i = (Q_i . S_start + sum_{j<=i} (q_i.k_j) v_j) / (q_i.Z_start + rowsum + eps)
__global__ void __launch_bounds__(256)
attn_kernel(const float* __restrict__ Q_, const float* __restrict__ K_,
            const float* __restrict__ V_, float* __restrict__ O_)
{
    int blk = blockIdx.x;
    int c = blk % NCH, bh = blk / NCH;
    int b = bh >> 3, hh = bh & 7;

    __shared__ float qs[CHK * DH];   // 16 KB
    __shared__ float ka[CHK * DH];   // K tile, reused for A after stage 1
    __shared__ float vsm[CHK * DH];

    int tid = threadIdx.x;
    for (int idx = tid * 4; idx < CHK * DH; idx += 256 * 4) {
        int t = idx >> 6, d = idx & 63;
        size_t gidx = ((size_t)(c * CHK + t) * B_SZ + b) * DM + hh * DH + d;
        *(float4*)&qs[idx]  = *(const float4*)&Q_[gidx];
        *(float4*)&ka[idx]  = *(const float4*)&K_[gidx];
        *(float4*)&vsm[idx] = *(const float4*)&V_[gidx];
    }
    __syncthreads();

    int i  = tid >> 2;           // output row within chunk
    int sub = tid & 3;
    int jb = sub << 4;           // this thread's 16-column j block

    // stage 1: A[i][j] = q_i . k_j for j <= i (keep in regs across the barrier)
    float areg[16];
    float rsum = 0.f;
    int nvalid = i - jb + 1;                     // how many j in [jb, jb+16) satisfy j<=i
    if (nvalid > 16) nvalid = 16;
    const float* qp = &qs[i * DH];
    #pragma unroll 4
    for (int jj = 0; jj < 16; jj++) {
        float a = 0.f;
        if (jj < nvalid) {
            const float* kp = &ka[(jb + jj) * DH];
            #pragma unroll
            for (int d = 0; d < DH; d += 4) {
                float4 qv = *(const float4*)&qp[d];
                float4 kv = *(const float4*)&kp[d];
                a += qv.x * kv.x + qv.y * kv.y + qv.z * kv.z + qv.w * kv.w;
            }
            rsum += a;
        }
        areg[jj] = a;
    }
    // row-sum across the 4 sub-lanes (consecutive lanes of same warp)
    rsum += __shfl_xor_sync(0xffffffffu, rsum, 1);
    rsum += __shfl_xor_sync(0xffffffffu, rsum, 2);

    __syncthreads();   // everyone done reading K
    #pragma unroll
    for (int jj = 0; jj < 16; jj++) ka[i * DH + jb + jj] = areg[jj];
    __syncthreads();

    // stage 2
    int mb = jb;    // 16 output dims per thread
    float acc[16] = {};
    for (int j = 0; j <= i; j++) {
        float a = ka[i * DH + j];
        const float* vp = &vsm[j * DH + mb];
        #pragma unroll
        for (int m = 0; m < 16; m += 4) {
            float4 vv = *(const float4*)&vp[m];
            acc[m + 0] += a * vv.x;
            acc[m + 1] += a * vv.y;
            acc[m + 2] += a * vv.z;
            acc[m + 3] += a * vv.w;
        }
    }

    const float* Sp = &g_S[((size_t)bh * NCH + c) * (DH * DH)];
    const float* Zp = &g_Z[((size_t)bh * NCH + c) * DH];
    float den = rsum + EPS_ATTN;
    for (int d = 0; d < DH; d++) {
        float qd = qp[d];
        den += qd * __ldg(&Zp[d]);
        const float* sp = &Sp[d * DH + mb];
        #pragma unroll
        for (int m = 0; m < 16; m += 4) {
            float4 sv = *(const float4*)__builtin_assume_aligned(&sp[m], 16);
            acc[m + 0] += qd * sv.x;
            acc[m + 1] += qd * sv.y;
            acc[m + 2] += qd * sv.z;
            acc[m + 3] += qd * sv.w;
        }
    }

    float inv = 1.f / den;
    size_t ob = ((size_t)(c * CHK + i) * B_SZ + b) * DM + hh * DH + mb;
    #pragma unroll
    for (int m = 0; m < 16; m += 4) {
        float4 o = {acc[m] * inv, acc[m + 1] * inv, acc[m + 2] * inv, acc[m + 3] * inv};
        *(float4*)&O_[ob + m] = o;
    }
}

// ---------------- host orchestration ----------------
extern "C" void kernel_launch(void* const* d_in, const int* in_sizes, int n_in,
                              void* d_out, int out_size)
{
    const int*   x   = (const int*)  d_in[0];
    const float* E   = (const float*)d_in[1];
    const float* Wq  = (const float*)d_in[2];
    const float* bq  = (const float*)d_in[3];
    const float* Wk  = (const float*)d_in[4];
    const float* bk  = (const float*)d_in[5];
    const float* Wv  = (const float*)d_in[6];
    const float* bv  = (const float*)d_in[7];
    const float* Wo  = (const float*)d_in[8];
    const float* bo  = (const float*)d_in[9];
    const float* g1  = (const float*)d_in[10];
    const float* be1 = (const float*)d_in[11];
    const float* W1  = (const float*)d_in[12];
    const float* b1  = (const float*)d_in[13];
    const float* W2  = (const float*)d_in[14];
    const float* b2  = (const float*)d_in[15];
    const float* g2  = (const float*)d_in[16];
    const float* be2 = (const float*)d_in[17];
    const float* Wp  = (const float*)d_in[18];
    const float* bp  = (const float*)d_in[19];
    float* out = (float*)d_out;

    float *ph, *pq, *pk, *pv, *pattn, *pff;
    cudaGetSymbolAddress((void**)&ph,    g_h);
    cudaGetSymbolAddress((void**)&pq,    g_q);
    cudaGetSymbolAddress((void**)&pk,    g_k);
    cudaGetSymbolAddress((void**)&pv,    g_v);
    cudaGetSymbolAddress((void**)&pattn, g_attn);
    cudaGetSymbolAddress((void**)&pff,   g_ff);

    embed_kernel<<<(MROWS * DM) / 256, 256>>>(x, E);

    dim3 gDM(DM / 64, MROWS / 64);
    dim3 gFF(DFF / 64, MROWS / 64);
    int nAttnBlk = NCH * B_SZ * NH;   // 8192

    for (int l = 0; l < NL; l++) {
        const float* wq = Wq + (size_t)l * DM * DM;
        const float* wk = Wk + (size_t)l * DM * DM;
        const float* wv = Wv + (size_t)l * DM * DM;
        const float* wo = Wo + (size_t)l * DM * DM;
        const float* w1 = W1 + (size_t)l * DM * DFF;
        const float* w2 = W2 + (size_t)l * DFF * DM;

        gemm_kernel<1, 0><<<gDM, 256>>>(ph, wq, bq + l * DM, pq, MROWS, DM, DM);
        gemm_kernel<1, 0><<<gDM, 256>>>(ph, wk, bk + l * DM, pk, MROWS, DM, DM);
        gemm_kernel<0, 0><<<gDM, 256>>>(ph, wv, bv + l * DM, pv, MROWS, DM, DM);

        chunk_sums_kernel<<<nAttnBlk, 256>>>(pk, pv);
        prefix_kernel<<<B_SZ * NH, 256>>>();
        attn_kernel<<<nAttnBlk, 256>>>(pq, pk, pv, pattn);

        gemm_kernel<0, 0><<<gDM, 256>>>(pattn, wo, bo + l * DM, pq, MROWS, DM, DM);
        ln_kernel<<<MROWS, 128>>>(ph, pq, g1 + l * DM, be1 + l * DM);

        gemm_kernel<2, 0><<<gFF, 256>>>(ph, w1, b1 + l * DFF, pff, MROWS, DFF, DM);
        gemm_kernel<0, 0><<<gDM, 256>>>(pff, w2, b2 + l * DM, pq, MROWS, DM, DFF);
        ln_kernel<<<MROWS, 128>>>(ph, pq, g2 + l * DM, be2 + l * DM);
    }

    dim3 gOut(NC / 64, MROWS / 64);
    gemm_kernel<0, 1><<<gOut, 256>>>(ph, Wp, bp, out, MROWS, NC, DM);
}

// round 3
// speedup vs baseline: 1.8770x; 1.8770x over previous
#include <cuda_runtime.h>
#include <math.h>
#include <stdio.h>

#define T_LEN 2048
#define B_SZ  32
#define DM    512
#define NH    8
#define DH    64
#define DFF   2048
#define NC    64
#define EV    256
#define DPE   256
#define NL    2
#define CHK   64
#define NCH   (T_LEN / CHK)          // 32
#define MROWS (T_LEN * B_SZ)         // 65536
#define EPS_ATTN 1e-6f
#define EPS_LN   1e-5f

// ---------------- scratch (device globals; no allocations allowed) ----------------
__device__ float g_h[MROWS * DM];        // 134 MB
__device__ float g_q[MROWS * DM];
__device__ float g_k[MROWS * DM];
__device__ float g_v[MROWS * DM];
__device__ float g_attn[MROWS * DM];
__device__ float g_ff[MROWS * DFF];      // 537 MB
__device__ float g_S[(size_t)B_SZ * NH * NCH * DH * DH];
__device__ float g_Z[(size_t)B_SZ * NH * NCH * DH];

// ---------------- embedding + positional encoding ----------------
__global__ void embed_kernel(const int* __restrict__ x, const float* __restrict__ E) {
    int idx = blockIdx.x * blockDim.x + threadIdx.x;
    int d  = idx & (DM - 1);
    int tb = idx >> 9;
    int b  = tb & (B_SZ - 1);
    int t  = tb >> 5;
    float val;
    if (d < EV) {
        val = E[(size_t)x[t * B_SZ + b] * EV + d];
    } else {
        int j = d - EV;
        float freq = expf((float)(j & ~1) * (-9.210340371976184f / 256.0f));
        float ang = (float)t * freq;
        val = (j & 1) ? cosf(ang) : sinf(ang);
    }
    g_h[idx] = val;
}

// ---------------- tf32 helpers ----------------
__device__ __forceinline__ unsigned f2tf(float f) {
    unsigned r;
    asm("cvt.rna.tf32.f32 %0, %1;" : "=r"(r) : "f"(f));
    return r;
}

__device__ __forceinline__ void mma_tf32(float* c, const unsigned* a, unsigned b0, unsigned b1) {
    asm volatile(
        "mma.sync.aligned.m16n8k8.row.col.f32.tf32.tf32.f32 "
        "{%0,%1,%2,%3}, {%4,%5,%6,%7}, {%8,%9}, {%0,%1,%2,%3};"
        : "+f"(c[0]), "+f"(c[1]), "+f"(c[2]), "+f"(c[3])
        : "r"(a[0]), "r"(a[1]), "r"(a[2]), "r"(a[3]), "r"(b0), "r"(b1));
}

// ---------------- tensor-core tf32 GEMM: C = act(A[M,K] @ W[K,N] + bias) ----------------
// Block tile 128(M) x BN(N). 256 threads = 8 warps as 4(M) x 2(N).
// Warp tile 32 x BN/2. ACT: 0 none, 1 elu+1, 2 relu.
#define ASTR 136   // smem k-row stride (floats): 8-bank shift per k-row -> conflict-free frags
template<int BN, int ACT>
__global__ void __launch_bounds__(256, 2)
mma_gemm_kernel(const float* __restrict__ A, const float* __restrict__ W,
                const float* __restrict__ bias, float* __restrict__ C,
                int M, int N, int K)
{
    constexpr int NT = BN / 16;       // 8-wide n-tiles per warp
    constexpr int WN = BN / 2;
    constexpr int NB4 = (16 * BN) / 1024;  // float4 B loads per thread per iter

    __shared__ unsigned As[2][16][ASTR];
    __shared__ unsigned Bs[2][16][ASTR];   // BN<=128 fits in 136-stride rows

    int tid = threadIdx.x;
    int bn = blockIdx.x * BN;
    int bm = blockIdx.y * 128;

    int wid = tid >> 5, lane = tid & 31;
    int wm = wid >> 1, wn = wid & 1;
    int g = lane >> 2, tg = lane & 3;

    // A loader mapping: tid<128 -> (m=tid, kq=0); tid>=128 -> (m=tid-128, kq=8)
    int am = tid & 127;
    int akq = (tid >> 7) << 3;
    const float* Ap = A + (size_t)(bm + am) * K + akq;

    float acc[2][NT][4];
    #pragma unroll
    for (int mt = 0; mt < 2; mt++)
        #pragma unroll
        for (int nt = 0; nt < NT; nt++)
            #pragma unroll
            for (int e = 0; e < 4; e++) acc[mt][nt][e] = 0.f;

    float4 apre0, apre1;
    float4 bpre[NB4];

    // prologue: load k0=0
    apre0 = *(const float4*)(Ap + 0);
    apre1 = *(const float4*)(Ap + 4);
    #pragma unroll
    for (int r = 0; r < NB4; r++) {
        int i = tid * 4 + r * 1024;
        int row = i / BN, col = i % BN;
        bpre[r] = *(const float4*)&W[(size_t)row * N + bn + col];
    }
    {
        unsigned* as = &As[0][akq][am];
        as[0 * ASTR] = f2tf(apre0.x); as[1 * ASTR] = f2tf(apre0.y);
        as[2 * ASTR] = f2tf(apre0.z); as[3 * ASTR] = f2tf(apre0.w);
        as[4 * ASTR] = f2tf(apre1.x); as[5 * ASTR] = f2tf(apre1.y);
        as[6 * ASTR] = f2tf(apre1.z); as[7 * ASTR] = f2tf(apre1.w);
        #pragma unroll
        for (int r = 0; r < NB4; r++) {
            int i = tid * 4 + r * 1024;
            int row = i / BN, col = i % BN;
            uint4 o = {f2tf(bpre[r].x), f2tf(bpre[r].y), f2tf(bpre[r].z), f2tf(bpre[r].w)};
            *(uint4*)&Bs[0][row][col] = o;
        }
    }
    __syncthreads();

    int buf = 0;
    for (int k0 = 0; k0 < K; k0 += 16) {
        bool has_next = (k0 + 16 < K);
        if (has_next) {
            const float* Apn = Ap + k0 + 16;
            apre0 = *(const float4*)(Apn + 0);
            apre1 = *(const float4*)(Apn + 4);
            #pragma unroll
            for (int r = 0; r < NB4; r++) {
                int i = tid * 4 + r * 1024;
                int row = i / BN, col = i % BN;
                bpre[r] = *(const float4*)&W[(size_t)(k0 + 16 + row) * N + bn + col];
            }
        }

        // compute 2 ksteps of 8 from smem[buf]
        #pragma unroll
        for (int kk = 0; kk < 2; kk++) {
            int kb = kk * 8;
            unsigned af[2][4];
            #pragma unroll
            for (int mt = 0; mt < 2; mt++) {
                int r0 = wm * 32 + mt * 16;
                af[mt][0] = As[buf][kb + tg][r0 + g];
                af[mt][1] = As[buf][kb + tg][r0 + g + 8];
                af[mt][2] = As[buf][kb + tg + 4][r0 + g];
                af[mt][3] = As[buf][kb + tg + 4][r0 + g + 8];
            }
            #pragma unroll
            for (int nt = 0; nt < NT; nt++) {
                int cb = wn * WN + nt * 8 + g;
                unsigned b0 = Bs[buf][kb + tg][cb];
                unsigned b1 = Bs[buf][kb + tg + 4][cb];
                mma_tf32(acc[0][nt], af[0], b0, b1);
                mma_tf32(acc[1][nt], af[1], b0, b1);
            }
        }

        if (has_next) {
            int nb = buf ^ 1;
            unsigned* as = &As[nb][akq][am];
            as[0 * ASTR] = f2tf(apre0.x); as[1 * ASTR] = f2tf(apre0.y);
            as[2 * ASTR] = f2tf(apre0.z); as[3 * ASTR] = f2tf(apre0.w);
            as[4 * ASTR] = f2tf(apre1.x); as[5 * ASTR] = f2tf(apre1.y);
            as[6 * ASTR] = f2tf(apre1.z); as[7 * ASTR] = f2tf(apre1.w);
            #pragma unroll
            for (int r = 0; r < NB4; r++) {
                int i = tid * 4 + r * 1024;
                int row = i / BN, col = i % BN;
                uint4 o = {f2tf(bpre[r].x), f2tf(bpre[r].y), f2tf(bpre[r].z), f2tf(bpre[r].w)};
                *(uint4*)&Bs[nb][row][col] = o;
            }
            __syncthreads();
            buf = nb;
        }
    }

    // epilogue: bias + activation, float2 stores
    #pragma unroll
    for (int mt = 0; mt < 2; mt++) {
        int row0 = bm + wm * 32 + mt * 16 + g;
        #pragma unroll
        for (int nt = 0; nt < NT; nt++) {
            int col = bn + wn * WN + nt * 8 + 2 * tg;
            float bi0 = bias[col], bi1 = bias[col + 1];
            float v0 = acc[mt][nt][0] + bi0;
            float v1 = acc[mt][nt][1] + bi1;
            float v2 = acc[mt][nt][2] + bi0;
            float v3 = acc[mt][nt][3] + bi1;
            if (ACT == 1) {
                v0 = (v0 > 0.f) ? (v0 + 1.f) : expf(v0);
                v1 = (v1 > 0.f) ? (v1 + 1.f) : expf(v1);
                v2 = (v2 > 0.f) ? (v2 + 1.f) : expf(v2);
                v3 = (v3 > 0.f) ? (v3 + 1.f) : expf(v3);
            }
            if (ACT == 2) {
                v0 = fmaxf(v0, 0.f); v1 = fmaxf(v1, 0.f);
                v2 = fmaxf(v2, 0.f); v3 = fmaxf(v3, 0.f);
            }
            float2 p0 = {v0, v1}, p1 = {v2, v3};
            *(float2*)&C[(size_t)row0 * N + col] = p0;
            *(float2*)&C[(size_t)(row0 + 8) * N + col] = p1;
        }
    }
}

// ---------------- old SIMT GEMM (kept only for the small final projection) ----------------
template<int ACT, int OUTMODE>
__global__ void __launch_bounds__(256)
gemm_kernel(const float* __restrict__ A, const float* __restrict__ W,
            const float* __restrict__ bias, float* __restrict__ C,
            int M, int N, int K)
{
    __shared__ float As[16][68];
    __shared__ float Bs[16][64];

    int tid = threadIdx.x;
    int bn = blockIdx.x * 64;
    int bm = blockIdx.y * 64;
    int tx = tid & 15, ty = tid >> 4;

    int arow = tid >> 2;
    int acol = (tid & 3) << 2;
    int brow = tid >> 4;
    int bcol = (tid & 15) << 2;

    const float* Ap = A + (size_t)(bm + arow) * K + acol;
    const float* Wp = W + (size_t)brow * N + bn + bcol;

    float acc[4][4] = {};

    for (int k0 = 0; k0 < K; k0 += 16) {
        float4 av = *(const float4*)Ap;  Ap += 16;
        float4 bv = *(const float4*)Wp;  Wp += (size_t)16 * N;
        As[acol + 0][arow] = av.x;
        As[acol + 1][arow] = av.y;
        As[acol + 2][arow] = av.z;
        As[acol + 3][arow] = av.w;
        *(float4*)&Bs[brow][bcol] = bv;
        __syncthreads();
        #pragma unroll
        for (int kk = 0; kk < 16; kk++) {
            float4 a4 = *(const float4*)&As[kk][ty << 2];
            float4 b4 = *(const float4*)&Bs[kk][tx << 2];
            float a[4] = {a4.x, a4.y, a4.z, a4.w};
            float b[4] = {b4.x, b4.y, b4.z, b4.w};
            #pragma unroll
            for (int i = 0; i < 4; i++)
                #pragma unroll
                for (int j = 0; j < 4; j++)
                    acc[i][j] += a[i] * b[j];
        }
        __syncthreads();
    }

    #pragma unroll
    for (int i = 0; i < 4; i++) {
        int row = bm + (ty << 2) + i;
        #pragma unroll
        for (int j = 0; j < 4; j++) {
            int col = bn + (tx << 2) + j;
            float val = acc[i][j] + bias[col];
            if (ACT == 1) val = (val > 0.f) ? (val + 1.f) : expf(val);
            if (ACT == 2) val = fmaxf(val, 0.f);
            if (OUTMODE == 0) {
                C[(size_t)row * N + col] = val;
            } else {
                int t = row >> 5, b = row & 31;
                C[((size_t)b * T_LEN + t) * NC + col] = val;
            }
        }
    }
}

// ---------------- residual add + LayerNorm (in place on h) ----------------
__global__ void __launch_bounds__(128)
ln_kernel(float* __restrict__ h, const float* __restrict__ addv,
          const float* __restrict__ g, const float* __restrict__ be)
{
    int row = blockIdx.x, tid = threadIdx.x;
    size_t base = (size_t)row * DM + (tid << 2);
    float4 hv = *(const float4*)&h[base];
    float4 av = *(const float4*)&addv[base];
    float x0 = hv.x + av.x, x1 = hv.y + av.y, x2 = hv.z + av.z, x3 = hv.w + av.w;

    __shared__ float red[4];
    int wid = tid >> 5, lane = tid & 31;

    float s = x0 + x1 + x2 + x3;
    #pragma unroll
    for (int o = 16; o > 0; o >>= 1) s += __shfl_xor_sync(0xffffffffu, s, o);
    if (lane == 0) red[wid] = s;
    __syncthreads();
    float mean = (red[0] + red[1] + red[2] + red[3]) * (1.0f / DM);

    float d0 = x0 - mean, d1 = x1 - mean, d2 = x2 - mean, d3 = x3 - mean;
    float vs = d0 * d0 + d1 * d1 + d2 * d2 + d3 * d3;
    #pragma unroll
    for (int o = 16; o > 0; o >>= 1) vs += __shfl_xor_sync(0xffffffffu, vs, o);
    __syncthreads();
    if (lane == 0) red[wid] = vs;
    __syncthreads();
    float var = (red[0] + red[1] + red[2] + red[3]) * (1.0f / DM);
    float inv = 1.0f / sqrtf(var + EPS_LN);

    int d = tid << 2;
    float4 gv = *(const float4*)&g[d];
    float4 bv = *(const float4*)&be[d];
    float4 o;
    o.x = d0 * inv * gv.x + bv.x;
    o.y = d1 * inv * gv.y + bv.y;
    o.z = d2 * inv * gv.z + bv.z;
    o.w = d3 * inv * gv.w + bv.w;
    *(float4*)&h[base] = o;
}

// ---------------- attention pass A: per-chunk KtV sums and K column sums ----------------
__global__ void __launch_bounds__(256)
chunk_sums_kernel(const float* __restrict__ K_, const float* __restrict__ V_)
{
    int blk = blockIdx.x;
    int c = blk % NCH, bh = blk / NCH;
    int b = bh >> 3, hh = bh & 7;

    __shared__ float ks[CHK * DH];
    __shared__ float vsm[CHK * DH];
    int tid = threadIdx.x;
    for (int idx = tid * 4; idx < CHK * DH; idx += 256 * 4) {
        int t = idx >> 6, d = idx & 63;
        size_t gidx = ((size_t)(c * CHK + t) * B_SZ + b) * DM + hh * DH + d;
        *(float4*)&ks[idx]  = *(const float4*)&K_[gidx];
        *(float4*)&vsm[idx] = *(const float4*)&V_[gidx];
    }
    __syncthreads();

    int d  = tid >> 2;
    int mb = (tid & 3) << 4;
    float acc[16] = {};
    float zacc = 0.f;
    for (int t = 0; t < CHK; t++) {
        float kd = ks[t * DH + d];
        zacc += kd;
        const float* vp = &vsm[t * DH + mb];
        #pragma unroll
        for (int m = 0; m < 16; m += 4) {
            float4 vv = *(const float4*)&vp[m];
            acc[m + 0] += kd * vv.x;
            acc[m + 1] += kd * vv.y;
            acc[m + 2] += kd * vv.z;
            acc[m + 3] += kd * vv.w;
        }
    }
    size_t sbase = ((size_t)bh * NCH + c) * (DH * DH) + d * DH + mb;
    #pragma unroll
    for (int m = 0; m < 16; m += 4) {
        float4 o = {acc[m], acc[m + 1], acc[m + 2], acc[m + 3]};
        *(float4*)&g_S[sbase + m] = o;
    }
    if ((tid & 3) == 0) g_Z[((size_t)bh * NCH + c) * DH + d] = zacc;
}

// ---------------- exclusive prefix over chunks (per b,h) ----------------
__global__ void __launch_bounds__(256)
prefix_kernel()
{
    int bh = blockIdx.x;
    int tid = threadIdx.x;
    float run[16] = {};
    for (int c = 0; c < NCH; c++) {
        size_t base = ((size_t)bh * NCH + c) * (DH * DH) + tid * 16;
        #pragma unroll
        for (int e = 0; e < 16; e++) {
            float t = g_S[base + e];
            g_S[base + e] = run[e];
            run[e] += t;
        }
    }
    if (tid < DH) {
        float rz = 0.f;
        for (int c = 0; c < NCH; c++) {
            size_t zi = ((size_t)bh * NCH + c) * DH + tid;
            float t = g_Z[zi];
            g_Z[zi] = rz;
            rz += t;
        }
    }
}

// ---------------- attention pass B: per-chunk causal output ----------------
__global__ void __launch_bounds__(256)
attn_kernel(const float* __restrict__ Q_, const float* __restrict__ K_,
            const float* __restrict__ V_, float* __restrict__ O_)
{
    int blk = blockIdx.x;
    int c = blk % NCH, bh = blk / NCH;
    int b = bh >> 3, hh = bh & 7;

    __shared__ float qs[CHK * DH];
    __shared__ float ka[CHK * DH];
    __shared__ float vsm[CHK * DH];

    int tid = threadIdx.x;
    for (int idx = tid * 4; idx < CHK * DH; idx += 256 * 4) {
        int t = idx >> 6, d = idx & 63;
        size_t gidx = ((size_t)(c * CHK + t) * B_SZ + b) * DM + hh * DH + d;
        *(float4*)&qs[idx]  = *(const float4*)&Q_[gidx];
        *(float4*)&ka[idx]  = *(const float4*)&K_[gidx];
        *(float4*)&vsm[idx] = *(const float4*)&V_[gidx];
    }
    __syncthreads();

    int i  = tid >> 2;
    int sub = tid & 3;
    int jb = sub << 4;

    float areg[16];
    float rsum = 0.f;
    int nvalid = i - jb + 1;
    if (nvalid > 16) nvalid = 16;
    const float* qp = &qs[i * DH];
    #pragma unroll 4
    for (int jj = 0; jj < 16; jj++) {
        float a = 0.f;
        if (jj < nvalid) {
            const float* kp = &ka[(jb + jj) * DH];
            #pragma unroll
            for (int d = 0; d < DH; d += 4) {
                float4 qv = *(const float4*)&qp[d];
                float4 kv = *(const float4*)&kp[d];
                a += qv.x * kv.x + qv.y * kv.y + qv.z * kv.z + qv.w * kv.w;
            }
            rsum += a;
        }
        areg[jj] = a;
    }
    rsum += __shfl_xor_sync(0xffffffffu, rsum, 1);
    rsum += __shfl_xor_sync(0xffffffffu, rsum, 2);

    __syncthreads();
    #pragma unroll
    for (int jj = 0; jj < 16; jj++) ka[i * DH + jb + jj] = areg[jj];
    __syncthreads();

    int mb = jb;
    float acc[16] = {};
    for (int j = 0; j <= i; j++) {
        float a = ka[i * DH + j];
        const float* vp = &vsm[j * DH + mb];
        #pragma unroll
        for (int m = 0; m < 16; m += 4) {
            float4 vv = *(const float4*)&vp[m];
            acc[m + 0] += a * vv.x;
            acc[m + 1] += a * vv.y;
            acc[m + 2] += a * vv.z;
            acc[m + 3] += a * vv.w;
        }
    }

    const float* Sp = &g_S[((size_t)bh * NCH + c) * (DH * DH)];
    const float* Zp = &g_Z[((size_t)bh * NCH + c) * DH];
    float den = rsum + EPS_ATTN;
    for (int d = 0; d < DH; d++) {
        float qd = qp[d];
        den += qd * __ldg(&Zp[d]);
        const float* sp = &Sp[d * DH + mb];
        #pragma unroll
        for (int m = 0; m < 16; m += 4) {
            float4 sv = *(const float4*)__builtin_assume_aligned(&sp[m], 16);
            acc[m + 0] += qd * sv.x;
            acc[m + 1] += qd * sv.y;
            acc[m + 2] += qd * sv.z;
            acc[m + 3] += qd * sv.w;
        }
    }

    float inv = 1.f / den;
    size_t ob = ((size_t)(c * CHK + i) * B_SZ + b) * DM + hh * DH + mb;
    #pragma unroll
    for (int m = 0; m < 16; m += 4) {
        float4 o = {acc[m] * inv, acc[m + 1] * inv, acc[m + 2] * inv, acc[m + 3] * inv};
        *(float4*)&O_[ob + m] = o;
    }
}

// ---------------- host orchestration ----------------
extern "C" void kernel_launch(void* const* d_in, const int* in_sizes, int n_in,
                              void* d_out, int out_size)
{
    const int*   x   = (const int*)  d_in[0];
    const float* E   = (const float*)d_in[1];
    const float* Wq  = (const float*)d_in[2];
    const float* bq  = (const float*)d_in[3];
    const float* Wk  = (const float*)d_in[4];
    const float* bk  = (const float*)d_in[5];
    const float* Wv  = (const float*)d_in[6];
    const float* bv  = (const float*)d_in[7];
    const float* Wo  = (const float*)d_in[8];
    const float* bo  = (const float*)d_in[9];
    const float* g1  = (const float*)d_in[10];
    const float* be1 = (const float*)d_in[11];
    const float* W1  = (const float*)d_in[12];
    const float* b1  = (const float*)d_in[13];
    const float* W2  = (const float*)d_in[14];
    const float* b2  = (const float*)d_in[15];
    const float* g2  = (const float*)d_in[16];
    const float* be2 = (const float*)d_in[17];
    const float* Wp  = (const float*)d_in[18];
    const float* bp  = (const float*)d_in[19];
    float* out = (float*)d_out;

    float *ph, *pq, *pk, *pv, *pattn, *pff;
    cudaGetSymbolAddress((void**)&ph,    g_h);
    cudaGetSymbolAddress((void**)&pq,    g_q);
    cudaGetSymbolAddress((void**)&pk,    g_k);
    cudaGetSymbolAddress((void**)&pv,    g_v);
    cudaGetSymbolAddress((void**)&pattn, g_attn);
    cudaGetSymbolAddress((void**)&pff,   g_ff);

    embed_kernel<<<(MROWS * DM) / 256, 256>>>(x, E);

    dim3 gDM(DM / 128, MROWS / 128);    // (4, 512)
    dim3 gFF(DFF / 128, MROWS / 128);   // (16, 512)
    int nAttnBlk = NCH * B_SZ * NH;     // 8192

    for (int l = 0; l < NL; l++) {
        const float* wq = Wq + (size_t)l * DM * DM;
        const float* wk = Wk + (size_t)l * DM * DM;
        const float* wv = Wv + (size_t)l * DM * DM;
        const float* wo = Wo + (size_t)l * DM * DM;
        const float* w1 = W1 + (size_t)l * DM * DFF;
        const float* w2 = W2 + (size_t)l * DFF * DM;

        mma_gemm_kernel<128, 1><<<gDM, 256>>>(ph, wq, bq + l * DM, pq, MROWS, DM, DM);
        mma_gemm_kernel<128, 1><<<gDM, 256>>>(ph, wk, bk + l * DM, pk, MROWS, DM, DM);
        mma_gemm_kernel<128, 0><<<gDM, 256>>>(ph, wv, bv + l * DM, pv, MROWS, DM, DM);

        chunk_sums_kernel<<<nAttnBlk, 256>>>(pk, pv);
        prefix_kernel<<<B_SZ * NH, 256>>>();
        attn_kernel<<<nAttnBlk, 256>>>(pq, pk, pv, pattn);

        mma_gemm_kernel<128, 0><<<gDM, 256>>>(pattn, wo, bo + l * DM, pq, MROWS, DM, DM);
        ln_kernel<<<MROWS, 128>>>(ph, pq, g1 + l * DM, be1 + l * DM);

        mma_gemm_kernel<128, 2><<<gFF, 256>>>(ph, w1, b1 + l * DFF, pff, MROWS, DFF, DM);
        mma_gemm_kernel<128, 0><<<gDM, 256>>>(pff, w2, b2 + l * DM, pq, MROWS, DM, DFF);
        ln_kernel<<<MROWS, 128>>>(ph, pq, g2 + l * DM, be2 + l * DM);
    }

    dim3 gOut(NC / 64, MROWS / 64);
    gemm_kernel<0, 1><<<gOut, 256>>>(ph, Wp, bp, out, MROWS, NC, DM);
}

// round 8
// speedup vs baseline: 2.1593x; 1.1503x over previous
#include <cuda_runtime.h>
#include <math.h>
#include <stdio.h>

#define T_LEN 2048
#define B_SZ  32
#define DM    512
#define NH    8
#define DH    64
#define DFF   2048
#define NC    64
#define EV    256
#define DPE   256
#define NL    2
#define CHK   64
#define NCH   (T_LEN / CHK)          // 32
#define MROWS (T_LEN * B_SZ)         // 65536
#define EPS_ATTN 1e-6f
#define EPS_LN   1e-5f

// ---------------- scratch (device globals; no allocations allowed) ----------------
__device__ float g_h[MROWS * DM];
__device__ float g_q[MROWS * DM];
__device__ float g_k[MROWS * DM];
__device__ float g_v[MROWS * DM];
__device__ float g_attn[MROWS * DM];
__device__ float g_ff[MROWS * DFF];
__device__ float g_S[(size_t)B_SZ * NH * NCH * DH * DH];
__device__ float g_Z[(size_t)B_SZ * NH * NCH * DH];

// ---------------- embedding + positional encoding ----------------
__global__ void embed_kernel(const int* __restrict__ x, const float* __restrict__ E) {
    int idx = blockIdx.x * blockDim.x + threadIdx.x;
    int d  = idx & (DM - 1);
    int tb = idx >> 9;
    int b  = tb & (B_SZ - 1);
    int t  = tb >> 5;
    float val;
    if (d < EV) {
        val = E[(size_t)x[t * B_SZ + b] * EV + d];
    } else {
        int j = d - EV;
        float freq = expf((float)(j & ~1) * (-9.210340371976184f / 256.0f));
        float ang = (float)t * freq;
        val = (j & 1) ? cosf(ang) : sinf(ang);
    }
    g_h[idx] = val;
}

// ---------------- tf32 helpers ----------------
__device__ __forceinline__ unsigned f2tf(float f) {
    unsigned r;
    asm("cvt.rna.tf32.f32 %0, %1;" : "=r"(r) : "f"(f));
    return r;
}

__device__ __forceinline__ void mma_tf32(float* c, const unsigned* a, unsigned b0, unsigned b1) {
    asm volatile(
        "mma.sync.aligned.m16n8k8.row.col.f32.tf32.tf32.f32 "
        "{%0,%1,%2,%3}, {%4,%5,%6,%7}, {%8,%9}, {%0,%1,%2,%3};"
        : "+f"(c[0]), "+f"(c[1]), "+f"(c[2]), "+f"(c[3])
        : "r"(a[0]), "r"(a[1]), "r"(a[2]), "r"(a[3]), "r"(b0), "r"(b1));
}

// ---------------- tensor-core tf32 GEMM: C = act(A[M,K] @ W[K,N] + bias) ----------------
// Block tile 128(M) x BN(N), 256 threads = 8 warps as 4(M) x 2(N), warp tile 32 x BN/2.
// k-PERMUTED smem layout: within each 8-k MMA step, k stored in order {0,4,1,5,2,6,3,7}
// so that fragment pairs (tg, tg+4) are physically adjacent -> all fragment reads LDS.64.
// Row stride 24 words: g*24 mod 32 cycles {0,24,16,8} -> conflict-free in each 16-lane phase.
// ACT: 0 none, 1 elu+1, 2 relu.  OUTMODE: 0 row-major, 1 transpose-to-[B][T][NC].
template<int BN, int ACT, int OUTMODE>
__global__ void __launch_bounds__(256, 2)
mma_gemm_kernel(const float* __restrict__ A, const float* __restrict__ W,
                const float* __restrict__ bias, float* __restrict__ C,
                int M, int N, int K)
{
    constexpr int NT = BN / 16;
    constexpr int WN = BN / 2;

    __shared__ unsigned As[2][128][24];
    __shared__ unsigned Bs[2][BN][24];

    int tid = threadIdx.x;
    int bn = blockIdx.x * BN;
    int bm = blockIdx.y * 128;

    int wid = tid >> 5, lane = tid & 31;
    int wm = wid >> 1, wn = wid & 1;
    int g = lane >> 2, tg = lane & 3;

    // A loader: thread handles row m = tid/2, k-half = (tid&1)*8  (32B-sector coalesced)
    int am = tid >> 1;
    int ak = (tid & 1) << 3;
    const float* Ap = A + (size_t)(bm + am) * K + ak;

    // B loader: thread handles column n = tid % BN, k-half = tid/BN (coalesced 4B per k-row)
    int bnl = tid % BN;
    int bkh = (tid / BN) & 1;
    bool bact = (tid < 2 * BN);
    const float* Wp = W + (size_t)(bkh * 8) * N + bn + bnl;

    float acc[2][NT][4] = {};

    float4 a0, a1;
    float bb[8];

    auto fetch = [&](int k0) {
        const float* ap = Ap + k0;
        a0 = *(const float4*)ap;
        a1 = *(const float4*)(ap + 4);
        if (bact) {
            const float* wp = Wp + (size_t)k0 * N;
            #pragma unroll
            for (int j = 0; j < 8; j++) bb[j] = wp[(size_t)j * N];
        }
    };

    auto stage = [&](int buf) {
        // permuted pack: phys {0..7} = logical k {0,4,1,5,2,6,3,7}
        uint4 alo = {f2tf(a0.x), f2tf(a1.x), f2tf(a0.y), f2tf(a1.y)};
        uint4 ahi = {f2tf(a0.z), f2tf(a1.z), f2tf(a0.w), f2tf(a1.w)};
        *(uint4*)&As[buf][am][ak + 0] = alo;
        *(uint4*)&As[buf][am][ak + 4] = ahi;
        if (bact) {
            uint4 blo = {f2tf(bb[0]), f2tf(bb[4]), f2tf(bb[1]), f2tf(bb[5])};
            uint4 bhi = {f2tf(bb[2]), f2tf(bb[6]), f2tf(bb[3]), f2tf(bb[7])};
            *(uint4*)&Bs[buf][bnl][bkh * 8 + 0] = blo;
            *(uint4*)&Bs[buf][bnl][bkh * 8 + 4] = bhi;
        }
    };

    fetch(0);
    stage(0);
    __syncthreads();

    int buf = 0;
    for (int k0 = 0; k0 < K; k0 += 16) {
        bool has_next = (k0 + 16 < K);
        if (has_next) fetch(k0 + 16);

        #pragma unroll
        for (int kk = 0; kk < 2; kk++) {
            int kb = kk * 8;
            unsigned af[2][4];
            #pragma unroll
            for (int mt = 0; mt < 2; mt++) {
                int r0 = wm * 32 + mt * 16;
                uint2 lo = *(const uint2*)&As[buf][r0 + g][kb + 2 * tg];
                uint2 hi = *(const uint2*)&As[buf][r0 + g + 8][kb + 2 * tg];
                af[mt][0] = lo.x; af[mt][1] = hi.x;
                af[mt][2] = lo.y; af[mt][3] = hi.y;
            }
            #pragma unroll
            for (int nt = 0; nt < NT; nt++) {
                int cb = wn * WN + nt * 8 + g;
                uint2 pb = *(const uint2*)&Bs[buf][cb][kb + 2 * tg];
                mma_tf32(acc[0][nt], af[0], pb.x, pb.y);
                mma_tf32(acc[1][nt], af[1], pb.x, pb.y);
            }
        }

        if (has_next) {
            int nb = buf ^ 1;
            stage(nb);
            __syncthreads();
            buf = nb;
        }
    }

    // epilogue: bias + activation, float2 stores
    #pragma unroll
    for (int mt = 0; mt < 2; mt++) {
        int row0 = bm + wm * 32 + mt * 16 + g;
        #pragma unroll
        for (int nt = 0; nt < NT; nt++) {
            int col = bn + wn * WN + nt * 8 + 2 * tg;
            float bi0 = bias[col], bi1 = bias[col + 1];
            float v0 = acc[mt][nt][0] + bi0;
            float v1 = acc[mt][nt][1] + bi1;
            float v2 = acc[mt][nt][2] + bi0;
            float v3 = acc[mt][nt][3] + bi1;
            if (ACT == 1) {
                v0 = (v0 > 0.f) ? (v0 + 1.f) : expf(v0);
                v1 = (v1 > 0.f) ? (v1 + 1.f) : expf(v1);
                v2 = (v2 > 0.f) ? (v2 + 1.f) : expf(v2);
                v3 = (v3 > 0.f) ? (v3 + 1.f) : expf(v3);
            }
            if (ACT == 2) {
                v0 = fmaxf(v0, 0.f); v1 = fmaxf(v1, 0.f);
                v2 = fmaxf(v2, 0.f); v3 = fmaxf(v3, 0.f);
            }
            float2 p0 = {v0, v1}, p1 = {v2, v3};
            if (OUTMODE == 0) {
                *(float2*)&C[(size_t)row0 * N + col] = p0;
                *(float2*)&C[(size_t)(row0 + 8) * N + col] = p1;
            } else {
                int t0 = row0 >> 5, b0i = row0 & 31;
                int t1 = (row0 + 8) >> 5, b1i = (row0 + 8) & 31;
                *(float2*)&C[((size_t)b0i * T_LEN + t0) * NC + col] = p0;
                *(float2*)&C[((size_t)b1i * T_LEN + t1) * NC + col] = p1;
            }
        }
    }
}

// ---------------- residual add + LayerNorm (in place on h) ----------------
__global__ void __launch_bounds__(128)
ln_kernel(float* __restrict__ h, const float* __restrict__ addv,
          const float* __restrict__ g, const float* __restrict__ be)
{
    int row = blockIdx.x, tid = threadIdx.x;
    size_t base = (size_t)row * DM + (tid << 2);
    float4 hv = *(const float4*)&h[base];
    float4 av = *(const float4*)&addv[base];
    float x0 = hv.x + av.x, x1 = hv.y + av.y, x2 = hv.z + av.z, x3 = hv.w + av.w;

    __shared__ float red[4];
    int wid = tid >> 5, lane = tid & 31;

    float s = x0 + x1 + x2 + x3;
    #pragma unroll
    for (int o = 16; o > 0; o >>= 1) s += __shfl_xor_sync(0xffffffffu, s, o);
    if (lane == 0) red[wid] = s;
    __syncthreads();
    float mean = (red[0] + red[1] + red[2] + red[3]) * (1.0f / DM);

    float d0 = x0 - mean, d1 = x1 - mean, d2 = x2 - mean, d3 = x3 - mean;
    float vs = d0 * d0 + d1 * d1 + d2 * d2 + d3 * d3;
    #pragma unroll
    for (int o = 16; o > 0; o >>= 1) vs += __shfl_xor_sync(0xffffffffu, vs, o);
    __syncthreads();
    if (lane == 0) red[wid] = vs;
    __syncthreads();
    float var = (red[0] + red[1] + red[2] + red[3]) * (1.0f / DM);
    float inv = 1.0f / sqrtf(var + EPS_LN);

    int d = tid << 2;
    float4 gv = *(const float4*)&g[d];
    float4 bv = *(const float4*)&be[d];
    float4 o;
    o.x = d0 * inv * gv.x + bv.x;
    o.y = d1 * inv * gv.y + bv.y;
    o.z = d2 * inv * gv.z + bv.z;
    o.w = d3 * inv * gv.w + bv.w;
    *(float4*)&h[base] = o;
}

// ---------------- attention pass A: per-chunk KtV sums and K column sums ----------------
__global__ void __launch_bounds__(256)
chunk_sums_kernel(const float* __restrict__ K_, const float* __restrict__ V_)
{
    int blk = blockIdx.x;
    int c = blk % NCH, bh = blk / NCH;
    int b = bh >> 3, hh = bh & 7;

    __shared__ float ks[CHK * DH];
    __shared__ float vsm[CHK * DH];
    int tid = threadIdx.x;
    for (int idx = tid * 4; idx < CHK * DH; idx += 256 * 4) {
        int t = idx >> 6, d = idx & 63;
        size_t gidx = ((size_t)(c * CHK + t) * B_SZ + b) * DM + hh * DH + d;
        *(float4*)&ks[idx]  = *(const float4*)&K_[gidx];
        *(float4*)&vsm[idx] = *(const float4*)&V_[gidx];
    }
    __syncthreads();

    int d  = tid >> 2;
    int mb = (tid & 3) << 4;
    float acc[16] = {};
    float zacc = 0.f;
    for (int t = 0; t < CHK; t++) {
        float kd = ks[t * DH + d];
        zacc += kd;
        const float* vp = &vsm[t * DH + mb];
        #pragma unroll
        for (int m = 0; m < 16; m += 4) {
            float4 vv = *(const float4*)&vp[m];
            acc[m + 0] += kd * vv.x;
            acc[m + 1] += kd * vv.y;
            acc[m + 2] += kd * vv.z;
            acc[m + 3] += kd * vv.w;
        }
    }
    size_t sbase = ((size_t)bh * NCH + c) * (DH * DH) + d * DH + mb;
    #pragma unroll
    for (int m = 0; m < 16; m += 4) {
        float4 o = {acc[m], acc[m + 1], acc[m + 2], acc[m + 3]};
        *(float4*)&g_S[sbase + m] = o;
    }
    if ((tid & 3) == 0) g_Z[((size_t)bh * NCH + c) * DH + d] = zacc;
}

// ---------------- exclusive prefix over chunks (per b,h) ----------------
__global__ void __launch_bounds__(256)
prefix_kernel()
{
    int bh = blockIdx.x;
    int tid = threadIdx.x;
    float run[16] = {};
    for (int c = 0; c < NCH; c++) {
        size_t base = ((size_t)bh * NCH + c) * (DH * DH) + tid * 16;
        #pragma unroll
        for (int e = 0; e < 16; e++) {
            float t = g_S[base + e];
            g_S[base + e] = run[e];
            run[e] += t;
        }
    }
    if (tid < DH) {
        float rz = 0.f;
        for (int c = 0; c < NCH; c++) {
            size_t zi = ((size_t)bh * NCH + c) * DH + tid;
            float t = g_Z[zi];
            g_Z[zi] = rz;
            rz += t;
        }
    }
}

// ---------------- attention pass B: per-chunk causal output ----------------
__global__ void __launch_bounds__(256)
attn_kernel(const float* __restrict__ Q_, const float* __restrict__ K_,
            const float* __restrict__ V_, float* __restrict__ O_)
{
    int blk = blockIdx.x;
    int c = blk % NCH, bh = blk / NCH;
    int b = bh >> 3, hh = bh & 7;

    __shared__ float qs[CHK * DH];
    __shared__ float ka[CHK * DH];
    __shared__ float vsm[CHK * DH];

    int tid = threadIdx.x;
    for (int idx = tid * 4; idx < CHK * DH; idx += 256 * 4) {
        int t = idx >> 6, d = idx & 63;
        size_t gidx = ((size_t)(c * CHK + t) * B_SZ + b) * DM + hh * DH + d;
        *(float4*)&qs[idx]  = *(const float4*)&Q_[gidx];
        *(float4*)&ka[idx]  = *(const float4*)&K_[gidx];
        *(float4*)&vsm[idx] = *(const float4*)&V_[gidx];
    }
    __syncthreads();

    int i  = tid >> 2;
    int sub = tid & 3;
    int jb = sub << 4;

    float areg[16];
    float rsum = 0.f;
    int nvalid = i - jb + 1;
    if (nvalid > 16) nvalid = 16;
    const float* qp = &qs[i * DH];
    #pragma unroll 4
    for (int jj = 0; jj < 16; jj++) {
        float a = 0.f;
        if (jj < nvalid) {
            const float* kp = &ka[(jb + jj) * DH];
            #pragma unroll
            for (int d = 0; d < DH; d += 4) {
                float4 qv = *(const float4*)&qp[d];
                float4 kv = *(const float4*)&kp[d];
                a += qv.x * kv.x + qv.y * kv.y + qv.z * kv.z + qv.w * kv.w;
            }
            rsum += a;
        }
        areg[jj] = a;
    }
    rsum += __shfl_xor_sync(0xffffffffu, rsum, 1);
    rsum += __shfl_xor_sync(0xffffffffu, rsum, 2);

    __syncthreads();
    #pragma unroll
    for (int jj = 0; jj < 16; jj++) ka[i * DH + jb + jj] = areg[jj];
    __syncthreads();

    int mb = jb;
    float acc[16] = {};
    for (int j = 0; j <= i; j++) {
        float a = ka[i * DH + j];
        const float* vp = &vsm[j * DH + mb];
        #pragma unroll
        for (int m = 0; m < 16; m += 4) {
            float4 vv = *(const float4*)&vp[m];
            acc[m + 0] += a * vv.x;
            acc[m + 1] += a * vv.y;
            acc[m + 2] += a * vv.z;
            acc[m + 3] += a * vv.w;
        }
    }

    const float* Sp = &g_S[((size_t)bh * NCH + c) * (DH * DH)];
    const float* Zp = &g_Z[((size_t)bh * NCH + c) * DH];
    float den = rsum + EPS_ATTN;
    for (int d = 0; d < DH; d++) {
        float qd = qp[d];
        den += qd * __ldg(&Zp[d]);
        const float* sp = &Sp[d * DH + mb];
        #pragma unroll
        for (int m = 0; m < 16; m += 4) {
            float4 sv = *(const float4*)__builtin_assume_aligned(&sp[m], 16);
            acc[m + 0] += qd * sv.x;
            acc[m + 1] += qd * sv.y;
            acc[m + 2] += qd * sv.z;
            acc[m + 3] += qd * sv.w;
        }
    }

    float inv = 1.f / den;
    size_t ob = ((size_t)(c * CHK + i) * B_SZ + b) * DM + hh * DH + mb;
    #pragma unroll
    for (int m = 0; m < 16; m += 4) {
        float4 o = {acc[m] * inv, acc[m + 1] * inv, acc[m + 2] * inv, acc[m + 3] * inv};
        *(float4*)&O_[ob + m] = o;
    }
}

// ---------------- host orchestration ----------------
extern "C" void kernel_launch(void* const* d_in, const int* in_sizes, int n_in,
                              void* d_out, int out_size)
{
    const int*   x   = (const int*)  d_in[0];
    const float* E   = (const float*)d_in[1];
    const float* Wq  = (const float*)d_in[2];
    const float* bq  = (const float*)d_in[3];
    const float* Wk  = (const float*)d_in[4];
    const float* bk  = (const float*)d_in[5];
    const float* Wv  = (const float*)d_in[6];
    const float* bv  = (const float*)d_in[7];
    const float* Wo  = (const float*)d_in[8];
    const float* bo  = (const float*)d_in[9];
    const float* g1  = (const float*)d_in[10];
    const float* be1 = (const float*)d_in[11];
    const float* W1  = (const float*)d_in[12];
    const float* b1  = (const float*)d_in[13];
    const float* W2  = (const float*)d_in[14];
    const float* b2  = (const float*)d_in[15];
    const float* g2  = (const float*)d_in[16];
    const float* be2 = (const float*)d_in[17];
    const float* Wp  = (const float*)d_in[18];
    const float* bp  = (const float*)d_in[19];
    float* out = (float*)d_out;

    float *ph, *pq, *pk, *pv, *pattn, *pff;
    cudaGetSymbolAddress((void**)&ph,    g_h);
    cudaGetSymbolAddress((void**)&pq,    g_q);
    cudaGetSymbolAddress((void**)&pk,    g_k);
    cudaGetSymbolAddress((void**)&pv,    g_v);
    cudaGetSymbolAddress((void**)&pattn, g_attn);
    cudaGetSymbolAddress((void**)&pff,   g_ff);

    embed_kernel<<<(MROWS * DM) / 256, 256>>>(x, E);

    dim3 gDM(DM / 128, MROWS / 128);    // (4, 512)
    dim3 gFF(DFF / 128, MROWS / 128);   // (16, 512)
    int nAttnBlk = NCH * B_SZ * NH;     // 8192

    for (int l = 0; l < NL; l++) {
        const float* wq = Wq + (size_t)l * DM * DM;
        const float* wk = Wk + (size_t)l * DM * DM;
        const float* wv = Wv + (size_t)l * DM * DM;
        const float* wo = Wo + (size_t)l * DM * DM;
        const float* w1 = W1 + (size_t)l * DM * DFF;
        const float* w2 = W2 + (size_t)l * DFF * DM;

        mma_gemm_kernel<128, 1, 0><<<gDM, 256>>>(ph, wq, bq + l * DM, pq, MROWS, DM, DM);
        mma_gemm_kernel<128, 1, 0><<<gDM, 256>>>(ph, wk, bk + l * DM, pk, MROWS, DM, DM);
        mma_gemm_kernel<128, 0, 0><<<gDM, 256>>>(ph, wv, bv + l * DM, pv, MROWS, DM, DM);

        chunk_sums_kernel<<<nAttnBlk, 256>>>(pk, pv);
        prefix_kernel<<<B_SZ * NH, 256>>>();
        attn_kernel<<<nAttnBlk, 256>>>(pq, pk, pv, pattn);

        mma_gemm_kernel<128, 0, 0><<<gDM, 256>>>(pattn, wo, bo + l * DM, pq, MROWS, DM, DM);
        ln_kernel<<<MROWS, 128>>>(ph, pq, g1 + l * DM, be1 + l * DM);

        mma_gemm_kernel<128, 2, 0><<<gFF, 256>>>(ph, w1, b1 + l * DFF, pff, MROWS, DFF, DM);
        mma_gemm_kernel<128, 0, 0><<<gDM, 256>>>(pff, w2, b2 + l * DM, pq, MROWS, DM, DFF);
        ln_kernel<<<MROWS, 128>>>(ph, pq, g2 + l * DM, be2 + l * DM);
    }

    dim3 gOut(1, MROWS / 128);
    mma_gemm_kernel<64, 0, 1><<<gOut, 256>>>(ph, Wp, bp, out, MROWS, NC, DM);
}

// round 10
// speedup vs baseline: 2.1789x; 1.0091x over previous
#include <cuda_runtime.h>
#include <math.h>

#define T_LEN 2048
#define B_SZ  32
#define DM    512
#define NH    8
#define DH    64
#define DFF   2048
#define NC    64
#define EV    256
#define NL    2
#define CHK   64
#define NCH   (T_LEN / CHK)          // 32
#define MROWS (T_LEN * B_SZ)         // 65536
#define EPS_ATTN 1e-6f
#define EPS_LN   1e-5f

// ---------------- scratch (device globals; no allocations allowed) ----------------
__device__ float g_h[MROWS * DM];
__device__ float g_q[MROWS * DM];
__device__ float g_k[MROWS * DM];
__device__ float g_v[MROWS * DM];
__device__ float g_attn[MROWS * DM];
__device__ float g_ff[MROWS * DFF];
__device__ float g_wtf[7 * 1024 * 1024];    // tf32-rounded weights

// offsets (floats) into g_wtf
#define WOFF_Q  0
#define WOFF_K  (2 * DM * DM)            // 524288
#define WOFF_V  (4 * DM * DM)
#define WOFF_O  (6 * DM * DM)
#define WOFF_1  (8 * DM * DM)            // 2097152
#define WOFF_2  (WOFF_1 + 2 * DM * DFF)  // 4194304
#define WOFF_P  (WOFF_2 + 2 * DM * DFF)  // 6291456

// ---------------- embedding + positional encoding ----------------
__global__ void embed_kernel(const int* __restrict__ x, const float* __restrict__ E) {
    int idx = blockIdx.x * blockDim.x + threadIdx.x;
    int d  = idx & (DM - 1);
    int tb = idx >> 9;
    int b  = tb & (B_SZ - 1);
    int t  = tb >> 5;
    float val;
    if (d < EV) {
        val = E[(size_t)x[t * B_SZ + b] * EV + d];
    } else {
        int j = d - EV;
        float freq = expf((float)(j & ~1) * (-9.210340371976184f / 256.0f));
        float ang = (float)t * freq;
        val = (j & 1) ? cosf(ang) : sinf(ang);
    }
    g_h[idx] = val;
}

// ---------------- tf32 helpers ----------------
__device__ __forceinline__ unsigned f2tf(float f) {
    unsigned r;
    asm("cvt.rna.tf32.f32 %0, %1;" : "=r"(r) : "f"(f));
    return r;
}

__device__ __forceinline__ void mma_tf32(float* c, const unsigned* a, unsigned b0, unsigned b1) {
    asm volatile(
        "mma.sync.aligned.m16n8k8.row.col.f32.tf32.tf32.f32 "
        "{%0,%1,%2,%3}, {%4,%5,%6,%7}, {%8,%9}, {%0,%1,%2,%3};"
        : "+f"(c[0]), "+f"(c[1]), "+f"(c[2]), "+f"(c[3])
        : "r"(a[0]), "r"(a[1]), "r"(a[2]), "r"(a[3]), "r"(b0), "r"(b1));
}

// ---------------- weight pre-rounding: dst = tf32_round(src), vectorized ----------------
__global__ void round_copy_kernel(const float* __restrict__ src, float* __restrict__ dst, int n4) {
    int idx = blockIdx.x * blockDim.x + threadIdx.x;
    if (idx < n4) {
        float4 v = ((const float4*)src)[idx];
        uint4 o = {f2tf(v.x), f2tf(v.y), f2tf(v.z), f2tf(v.w)};
        ((uint4*)dst)[idx] = o;
    }
}

// ---------------- tensor-core tf32 GEMM: C = act(A[M,K] @ W[K,N] + bias) ----------------
// Block tile 128(M) x BN(N), 256 threads = 8 warps as 4(M) x 2(N), warp tile 32 x BN/2.
// k-PERMUTED smem: within each 8-k step, k stored {0,4,1,5,2,6,3,7} -> LDS.64 fragments.
// W must be PRE-ROUNDED to tf32 (g_wtf). N,K compile-time -> imm-offset B loads.
// ACT: 0 none, 1 elu+1, 2 relu.  OUTMODE: 0 row-major, 1 transpose-to-[B][T][NC].
template<int BN, int ACT, int OUTMODE, int NN, int KK>
__global__ void __launch_bounds__(256, 2)
mma_gemm_kernel(const float* __restrict__ A, const float* __restrict__ W,
                const float* __restrict__ bias, float* __restrict__ C)
{
    constexpr int NT = BN / 16;
    constexpr int WN = BN / 2;

    __shared__ unsigned As[2][128][24];
    __shared__ unsigned Bs[2][BN][24];

    int tid = threadIdx.x;
    int bn = blockIdx.x * BN;
    int bm = blockIdx.y * 128;

    int wid = tid >> 5, lane = tid & 31;
    int wm = wid >> 1, wn = wid & 1;
    int g = lane >> 2, tg = lane & 3;

    int am = tid >> 1;
    int ak = (tid & 1) << 3;
    const float* Ap = A + (size_t)(bm + am) * KK + ak;

    int bnl = tid % BN;
    int bkh = (tid / BN) & 1;
    bool bact = (tid < 2 * BN);
    const float* Wp = W + (size_t)(bkh * 8) * NN + bn + bnl;

    float acc[2][NT][4] = {};

    float4 a0, a1;
    float bb[8];

    auto fetch = [&](int k0) {
        const float* ap = Ap + k0;
        a0 = *(const float4*)ap;
        a1 = *(const float4*)(ap + 4);
        if (bact) {
            const float* wp = Wp + (size_t)k0 * NN;
            #pragma unroll
            for (int j = 0; j < 8; j++) bb[j] = wp[j * NN];
        }
    };

    auto stage = [&](int buf) {
        uint4 alo = {f2tf(a0.x), f2tf(a1.x), f2tf(a0.y), f2tf(a1.y)};
        uint4 ahi = {f2tf(a0.z), f2tf(a1.z), f2tf(a0.w), f2tf(a1.w)};
        *(uint4*)&As[buf][am][ak + 0] = alo;
        *(uint4*)&As[buf][am][ak + 4] = ahi;
        if (bact) {
            // W pre-rounded: store raw bits (no cvt)
            uint4 blo = {__float_as_uint(bb[0]), __float_as_uint(bb[4]),
                         __float_as_uint(bb[1]), __float_as_uint(bb[5])};
            uint4 bhi = {__float_as_uint(bb[2]), __float_as_uint(bb[6]),
                         __float_as_uint(bb[3]), __float_as_uint(bb[7])};
            *(uint4*)&Bs[buf][bnl][bkh * 8 + 0] = blo;
            *(uint4*)&Bs[buf][bnl][bkh * 8 + 4] = bhi;
        }
    };

    fetch(0);
    stage(0);
    __syncthreads();

    int buf = 0;
    #pragma unroll 1
    for (int k0 = 0; k0 < KK; k0 += 16) {
        bool has_next = (k0 + 16 < KK);
        if (has_next) fetch(k0 + 16);

        #pragma unroll
        for (int kk = 0; kk < 2; kk++) {
            int kb = kk * 8;
            unsigned af[2][4];
            #pragma unroll
            for (int mt = 0; mt < 2; mt++) {
                int r0 = wm * 32 + mt * 16;
                uint2 lo = *(const uint2*)&As[buf][r0 + g][kb + 2 * tg];
                uint2 hi = *(const uint2*)&As[buf][r0 + g + 8][kb + 2 * tg];
                af[mt][0] = lo.x; af[mt][1] = hi.x;
                af[mt][2] = lo.y; af[mt][3] = hi.y;
            }
            #pragma unroll
            for (int nt = 0; nt < NT; nt++) {
                int cb = wn * WN + nt * 8 + g;
                uint2 pb = *(const uint2*)&Bs[buf][cb][kb + 2 * tg];
                mma_tf32(acc[0][nt], af[0], pb.x, pb.y);
                mma_tf32(acc[1][nt], af[1], pb.x, pb.y);
            }
        }

        if (has_next) {
            int nb = buf ^ 1;
            stage(nb);
            __syncthreads();
            buf = nb;
        }
    }

    #pragma unroll
    for (int mt = 0; mt < 2; mt++) {
        int row0 = bm + wm * 32 + mt * 16 + g;
        #pragma unroll
        for (int nt = 0; nt < NT; nt++) {
            int col = bn + wn * WN + nt * 8 + 2 * tg;
            float bi0 = bias[col], bi1 = bias[col + 1];
            float v0 = acc[mt][nt][0] + bi0;
            float v1 = acc[mt][nt][1] + bi1;
            float v2 = acc[mt][nt][2] + bi0;
            float v3 = acc[mt][nt][3] + bi1;
            if (ACT == 1) {
                v0 = (v0 > 0.f) ? (v0 + 1.f) : expf(v0);
                v1 = (v1 > 0.f) ? (v1 + 1.f) : expf(v1);
                v2 = (v2 > 0.f) ? (v2 + 1.f) : expf(v2);
                v3 = (v3 > 0.f) ? (v3 + 1.f) : expf(v3);
            }
            if (ACT == 2) {
                v0 = fmaxf(v0, 0.f); v1 = fmaxf(v1, 0.f);
                v2 = fmaxf(v2, 0.f); v3 = fmaxf(v3, 0.f);
            }
            float2 p0 = {v0, v1}, p1 = {v2, v3};
            if (OUTMODE == 0) {
                *(float2*)&C[(size_t)row0 * NN + col] = p0;
                *(float2*)&C[(size_t)(row0 + 8) * NN + col] = p1;
            } else {
                int t0 = row0 >> 5, b0i = row0 & 31;
                int t1 = (row0 + 8) >> 5, b1i = (row0 + 8) & 31;
                *(float2*)&C[((size_t)b0i * T_LEN + t0) * NC + col] = p0;
                *(float2*)&C[((size_t)b1i * T_LEN + t1) * NC + col] = p1;
            }
        }
    }
}

// ---------------- residual add + LayerNorm (in place on h) ----------------
__global__ void __launch_bounds__(128)
ln_kernel(float* __restrict__ h, const float* __restrict__ addv,
          const float* __restrict__ g, const float* __restrict__ be)
{
    int row = blockIdx.x, tid = threadIdx.x;
    size_t base = (size_t)row * DM + (tid << 2);
    float4 hv = *(const float4*)&h[base];
    float4 av = *(const float4*)&addv[base];
    float x0 = hv.x + av.x, x1 = hv.y + av.y, x2 = hv.z + av.z, x3 = hv.w + av.w;

    __shared__ float red[4];
    int wid = tid >> 5, lane = tid & 31;

    float s = x0 + x1 + x2 + x3;
    #pragma unroll
    for (int o = 16; o > 0; o >>= 1) s += __shfl_xor_sync(0xffffffffu, s, o);
    if (lane == 0) red[wid] = s;
    __syncthreads();
    float mean = (red[0] + red[1] + red[2] + red[3]) * (1.0f / DM);

    float d0 = x0 - mean, d1 = x1 - mean, d2 = x2 - mean, d3 = x3 - mean;
    float vs = d0 * d0 + d1 * d1 + d2 * d2 + d3 * d3;
    #pragma unroll
    for (int o = 16; o > 0; o >>= 1) vs += __shfl_xor_sync(0xffffffffu, vs, o);
    __syncthreads();
    if (lane == 0) red[wid] = vs;
    __syncthreads();
    float var = (red[0] + red[1] + red[2] + red[3]) * (1.0f / DM);
    float inv = 1.0f / sqrtf(var + EPS_LN);

    int d = tid << 2;
    float4 gv = *(const float4*)&g[d];
    float4 bv = *(const float4*)&be[d];
    float4 o;
    o.x = d0 * inv * gv.x + bv.x;
    o.y = d1 * inv * gv.y + bv.y;
    o.z = d2 * inv * gv.z + bv.z;
    o.w = d3 * inv * gv.w + bv.w;
    *(float4*)&h[base] = o;
}

// ---------------- FUSED attention: one block per (b,h), S/Z carried in smem ----------------
// Per chunk (exclusive-prefix order):
//   phase L: load q,k,v tiles
//   phase 1: A=tril(QK^T) in regs, rsum; acc = q.S_old, den = rsum + q.Z_old; store A to smem
//   phase 2: acc += A.V, write out; S += K^T V, Z += colsum(K)  (each thread owns its S slice)
__global__ void __launch_bounds__(256)
fused_attn_kernel(const float* __restrict__ Q_, const float* __restrict__ K_,
                  const float* __restrict__ V_, float* __restrict__ O_)
{
    extern __shared__ float sm[];
    float* S   = sm;                         // 64*64
    float* Zs  = sm + CHK * DH;              // 64
    float* qs  = Zs + DH;                    // 64*64
    float* ks  = qs + CHK * DH;
    float* vsm = ks + CHK * DH;
    float* asb = vsm + CHK * DH;             // A buffer 64*64

    int bh = blockIdx.x;
    int b = bh >> 3, hh = bh & 7;
    int tid = threadIdx.x;

    // init S, Z
    for (int idx = tid; idx < CHK * DH; idx += 256) S[idx] = 0.f;
    if (tid < DH) Zs[tid] = 0.f;

    int i   = tid >> 2;          // row within chunk (and d-index for S update)
    int sub = tid & 3;
    int jb  = sub << 4;          // 16-col j block / m block
    int mb  = jb;

    for (int c = 0; c < NCH; c++) {
        __syncthreads();   // S init / prev-iter tile readers done before overwrite

        for (int idx = tid * 4; idx < CHK * DH; idx += 256 * 4) {
            int t = idx >> 6, d = idx & 63;
            size_t gidx = ((size_t)(c * CHK + t) * B_SZ + b) * DM + hh * DH + d;
            *(float4*)&qs[idx]  = *(const float4*)&Q_[gidx];
            *(float4*)&ks[idx]  = *(const float4*)&K_[gidx];
            *(float4*)&vsm[idx] = *(const float4*)&V_[gidx];
        }
        __syncthreads();

        // phase 1: intra scores + old-state contribution
        float areg[16];
        float rsum = 0.f;
        int nvalid = i - jb + 1;
        if (nvalid > 16) nvalid = 16;
        const float* qp = &qs[i * DH];
        #pragma unroll 4
        for (int jj = 0; jj < 16; jj++) {
            float a = 0.f;
            if (jj < nvalid) {
                const float* kp = &ks[(jb + jj) * DH];
                #pragma unroll
                for (int d = 0; d < DH; d += 4) {
                    float4 qv = *(const float4*)&qp[d];
                    float4 kv = *(const float4*)&kp[d];
                    a += qv.x * kv.x + qv.y * kv.y + qv.z * kv.z + qv.w * kv.w;
                }
                rsum += a;
            }
            areg[jj] = a;
        }
        rsum += __shfl_xor_sync(0xffffffffu, rsum, 1);
        rsum += __shfl_xor_sync(0xffffffffu, rsum, 2);

        float acc[16] = {};
        float den = rsum + EPS_ATTN;
        for (int d = 0; d < DH; d++) {
            float qd = qp[d];
            den += qd * Zs[d];
            const float* sp = &S[d * DH + mb];
            #pragma unroll
            for (int m = 0; m < 16; m += 4) {
                float4 sv = *(const float4*)&sp[m];
                acc[m + 0] += qd * sv.x;
                acc[m + 1] += qd * sv.y;
                acc[m + 2] += qd * sv.z;
                acc[m + 3] += qd * sv.w;
            }
        }

        #pragma unroll
        for (int jj = 0; jj < 16; jj++) asb[i * DH + jb + jj] = areg[jj];
        __syncthreads();   // A visible; all q.S_old reads complete -> S writable

        // phase 2a: intra A.V + output
        for (int j = 0; j <= i; j++) {
            float a = asb[i * DH + j];
            const float* vp = &vsm[j * DH + mb];
            #pragma unroll
            for (int m = 0; m < 16; m += 4) {
                float4 vv = *(const float4*)&vp[m];
                acc[m + 0] += a * vv.x;
                acc[m + 1] += a * vv.y;
                acc[m + 2] += a * vv.z;
                acc[m + 3] += a * vv.w;
            }
        }
        float inv = 1.f / den;
        size_t ob = ((size_t)(c * CHK + i) * B_SZ + b) * DM + hh * DH + mb;
        #pragma unroll
        for (int m = 0; m < 16; m += 4) {
            float4 o = {acc[m] * inv, acc[m + 1] * inv, acc[m + 2] * inv, acc[m + 3] * inv};
            *(float4*)&O_[ob + m] = o;
        }

        // phase 2b: state update (thread owns (d=i, mb) slice exclusively)
        float up[16] = {};
        float zup = 0.f;
        for (int t = 0; t < CHK; t++) {
            float kd = ks[t * DH + i];
            zup += kd;
            const float* vp = &vsm[t * DH + mb];
            #pragma unroll
            for (int m = 0; m < 16; m += 4) {
                float4 vv = *(const float4*)&vp[m];
                up[m + 0] += kd * vv.x;
                up[m + 1] += kd * vv.y;
                up[m + 2] += kd * vv.z;
                up[m + 3] += kd * vv.w;
            }
        }
        float* srow = &S[i * DH + mb];
        #pragma unroll
        for (int m = 0; m < 16; m += 4) {
            float4 sv = *(const float4*)&srow[m];
            sv.x += up[m + 0]; sv.y += up[m + 1];
            sv.z += up[m + 2]; sv.w += up[m + 3];
            *(float4*)&srow[m] = sv;
        }
        if (sub == 0) Zs[i] += zup;
    }
}

#define ATT_SMEM ((5 * CHK * DH + DH) * (int)sizeof(float))   // 82176 B

// ---------------- host orchestration ----------------
extern "C" void kernel_launch(void* const* d_in, const int* in_sizes, int n_in,
                              void* d_out, int out_size)
{
    const int*   x   = (const int*)  d_in[0];
    const float* E   = (const float*)d_in[1];
    const float* Wq  = (const float*)d_in[2];
    const float* bq  = (const float*)d_in[3];
    const float* Wk  = (const float*)d_in[4];
    const float* bk  = (const float*)d_in[5];
    const float* Wv  = (const float*)d_in[6];
    const float* bv  = (const float*)d_in[7];
    const float* Wo  = (const float*)d_in[8];
    const float* bo  = (const float*)d_in[9];
    const float* g1  = (const float*)d_in[10];
    const float* be1 = (const float*)d_in[11];
    const float* W1  = (const float*)d_in[12];
    const float* b1  = (const float*)d_in[13];
    const float* W2  = (const float*)d_in[14];
    const float* b2  = (const float*)d_in[15];
    const float* g2  = (const float*)d_in[16];
    const float* be2 = (const float*)d_in[17];
    const float* Wp  = (const float*)d_in[18];
    const float* bp  = (const float*)d_in[19];
    float* out = (float*)d_out;

    float *ph, *pq, *pk, *pv, *pattn, *pff, *pw;
    cudaGetSymbolAddress((void**)&ph,    g_h);
    cudaGetSymbolAddress((void**)&pq,    g_q);
    cudaGetSymbolAddress((void**)&pk,    g_k);
    cudaGetSymbolAddress((void**)&pv,    g_v);
    cudaGetSymbolAddress((void**)&pattn, g_attn);
    cudaGetSymbolAddress((void**)&pff,   g_ff);
    cudaGetSymbolAddress((void**)&pw,    g_wtf);

    static bool attr_done = false;
    if (!attr_done) {
        cudaFuncSetAttribute(fused_attn_kernel,
                             cudaFuncAttributeMaxDynamicSharedMemorySize, ATT_SMEM);
        attr_done = true;
    }

    // pre-round weights to tf32 (idempotent w.r.t. previous in-GEMM cvt -> numerics identical)
    {
        auto rc = [&](const float* src, float* dst, int n) {
            int n4 = n / 4;
            round_copy_kernel<<<(n4 + 255) / 256, 256>>>(src, dst, n4);
        };
        rc(Wq, pw + WOFF_Q, 2 * DM * DM);
        rc(Wk, pw + WOFF_K, 2 * DM * DM);
        rc(Wv, pw + WOFF_V, 2 * DM * DM);
        rc(Wo, pw + WOFF_O, 2 * DM * DM);
        rc(W1, pw + WOFF_1, 2 * DM * DFF);
        rc(W2, pw + WOFF_2, 2 * DFF * DM);
        rc(Wp, pw + WOFF_P, DM * NC);
    }

    embed_kernel<<<(MROWS * DM) / 256, 256>>>(x, E);

    dim3 gDM(DM / 128, MROWS / 128);    // (4, 512)
    dim3 gFF(DFF / 128, MROWS / 128);   // (16, 512)

    for (int l = 0; l < NL; l++) {
        const float* wq = pw + WOFF_Q + (size_t)l * DM * DM;
        const float* wk = pw + WOFF_K + (size_t)l * DM * DM;
        const float* wv = pw + WOFF_V + (size_t)l * DM * DM;
        const float* wo = pw + WOFF_O + (size_t)l * DM * DM;
        const float* w1 = pw + WOFF_1 + (size_t)l * DM * DFF;
        const float* w2 = pw + WOFF_2 + (size_t)l * DFF * DM;

        mma_gemm_kernel<128, 1, 0, DM, DM><<<gDM, 256>>>(ph, wq, bq + l * DM, pq);
        mma_gemm_kernel<128, 1, 0, DM, DM><<<gDM, 256>>>(ph, wk, bk + l * DM, pk);
        mma_gemm_kernel<128, 0, 0, DM, DM><<<gDM, 256>>>(ph, wv, bv + l * DM, pv);

        fused_attn_kernel<<<B_SZ * NH, 256, ATT_SMEM>>>(pq, pk, pv, pattn);

        mma_gemm_kernel<128, 0, 0, DM, DM><<<gDM, 256>>>(pattn, wo, bo + l * DM, pq);
        ln_kernel<<<MROWS, 128>>>(ph, pq, g1 + l * DM, be1 + l * DM);

        mma_gemm_kernel<128, 2, 0, DFF, DM><<<gFF, 256>>>(ph, w1, b1 + l * DFF, pff);
        mma_gemm_kernel<128, 0, 0, DM, DFF><<<gDM, 256>>>(pff, w2, b2 + l * DM, pq);
        ln_kernel<<<MROWS, 128>>>(ph, pq, g2 + l * DM, be2 + l * DM);
    }

    dim3 gOut(1, MROWS / 128);
    mma_gemm_kernel<64, 0, 1, NC, DM><<<gOut, 256>>>(ph, pw + WOFF_P, bp, out);
}

// round 11
// speedup vs baseline: 2.9646x; 1.3606x over previous
#include <cuda_runtime.h>
#include <math.h>

#define T_LEN 2048
#define B_SZ  32
#define DM    512
#define NH    8
#define DH    64
#define DFF   2048
#define NC    64
#define EV    256
#define NL    2
#define CHK   64
#define NCH   (T_LEN / CHK)          // 32
#define MROWS (T_LEN * B_SZ)         // 65536
#define EPS_ATTN 1e-6f
#define EPS_LN   1e-5f

// ---------------- scratch (device globals; no allocations allowed) ----------------
__device__ float g_h[MROWS * DM];
__device__ float g_q[MROWS * DM];
__device__ float g_k[MROWS * DM];
__device__ float g_v[MROWS * DM];
__device__ float g_attn[MROWS * DM];
__device__ float g_ff[MROWS * DFF];
__device__ float g_wtf[7 * 1024 * 1024];    // tf32-rounded, slab-permuted weights

// offsets (floats) into g_wtf
#define WOFF_Q  0
#define WOFF_K  (2 * DM * DM)
#define WOFF_V  (4 * DM * DM)
#define WOFF_O  (6 * DM * DM)
#define WOFF_1  (8 * DM * DM)
#define WOFF_2  (WOFF_1 + 2 * DM * DFF)
#define WOFF_P  (WOFF_2 + 2 * DM * DFF)

// ---------------- embedding + positional encoding ----------------
__global__ void embed_kernel(const int* __restrict__ x, const float* __restrict__ E) {
    int idx = blockIdx.x * blockDim.x + threadIdx.x;
    int d  = idx & (DM - 1);
    int tb = idx >> 9;
    int b  = tb & (B_SZ - 1);
    int t  = tb >> 5;
    float val;
    if (d < EV) {
        val = E[(size_t)x[t * B_SZ + b] * EV + d];
    } else {
        int j = d - EV;
        float freq = expf((float)(j & ~1) * (-9.210340371976184f / 256.0f));
        float ang = (float)t * freq;
        val = (j & 1) ? cosf(ang) : sinf(ang);
    }
    g_h[idx] = val;
}

// ---------------- tf32 + cp.async helpers ----------------
__device__ __forceinline__ unsigned f2tf(float f) {
    unsigned r;
    asm("cvt.rna.tf32.f32 %0, %1;" : "=r"(r) : "f"(f));
    return r;
}

__device__ __forceinline__ void mma_tf32(float* c, const unsigned* a, unsigned b0, unsigned b1) {
    asm volatile(
        "mma.sync.aligned.m16n8k8.row.col.f32.tf32.tf32.f32 "
        "{%0,%1,%2,%3}, {%4,%5,%6,%7}, {%8,%9}, {%0,%1,%2,%3};"
        : "+f"(c[0]), "+f"(c[1]), "+f"(c[2]), "+f"(c[3])
        : "r"(a[0]), "r"(a[1]), "r"(a[2]), "r"(a[3]), "r"(b0), "r"(b1));
}

__device__ __forceinline__ unsigned smem_u32(const void* p) {
    return (unsigned)__cvta_generic_to_shared(p);
}
#define CP_ASYNC16(dst, src) \
    asm volatile("cp.async.ca.shared.global [%0], [%1], 16;" :: "r"(dst), "l"(src))
#define CP_COMMIT() asm volatile("cp.async.commit_group;")
#define CP_WAIT0()  asm volatile("cp.async.wait_group 0;")

// ---------------- weight prep: tf32-round + slab-permute into smem image layout ----------
// dst[(s*N + n)*16 + w] = tf32( src[(16s + lk(w))*N + n] ),  lk(w) = ((w&7)>>1)+((w&1)<<2)+(w&8)
__global__ void prep_w_kernel(const float* __restrict__ src, float* __restrict__ dst,
                              int N, int K) {
    int idx = blockIdx.x * blockDim.x + threadIdx.x;
    int total = (K >> 4) * N;
    if (idx >= total) return;
    int n = idx % N;
    int s = idx / N;
    const float* sp = src + ((size_t)(s << 4)) * N + n;
    float o[16];
    #pragma unroll
    for (int w = 0; w < 16; w++) {
        int lk = ((w & 7) >> 1) + ((w & 1) << 2) + (w & 8);
        o[w] = __uint_as_float(f2tf(sp[(size_t)lk * N]));
    }
    float* dp = dst + ((size_t)idx << 4);
    #pragma unroll
    for (int v = 0; v < 4; v++)
        *(float4*)&dp[4 * v] = make_float4(o[4*v], o[4*v+1], o[4*v+2], o[4*v+3]);
}

// ---------------- tensor-core tf32 GEMM: C = act(A[M,K] @ W[K,N] + bias) ----------------
// Block 128 x BN, 256 threads = 8 warps (4M x 2N), warp tile 32 x BN/2.
// A: LDG->cvt->STS with k-permuted {0,4,1,5,2,6,3,7|+8} rows, stride 24 (proven clean frags).
// B: cp.async 16B chunks from PRE-PERMUTED g_wtf slab image straight into Bs (no regs/cvt/STS).
template<int BN, int ACT, int OUTMODE, int NN, int KK>
__global__ void __launch_bounds__(256, 2)
mma_gemm_kernel(const float* __restrict__ A, const float* __restrict__ W,
                const float* __restrict__ bias, float* __restrict__ C)
{
    constexpr int NT = BN / 16;
    constexpr int WN = BN / 2;
    constexpr int CH = BN / 64;     // cp.async chunks per thread per slab

    __shared__ unsigned As[2][128][24];
    __shared__ unsigned Bs[2][BN][24];

    int tid = threadIdx.x;
    int bn = blockIdx.x * BN;
    int bm = blockIdx.y * 128;

    int wid = tid >> 5, lane = tid & 31;
    int wm = wid >> 1, wn = wid & 1;
    int g = lane >> 2, tg = lane & 3;

    int am = tid >> 1;
    int ak = (tid & 1) << 3;
    const float* Ap = A + (size_t)(bm + am) * KK + ak;

    float acc[2][NT][4] = {};
    float4 a0, a1;

    auto fetchA = [&](int k0) {
        const float* ap = Ap + k0;
        a0 = *(const float4*)ap;
        a1 = *(const float4*)(ap + 4);
    };
    auto stageA = [&](int buf) {
        uint4 alo = {f2tf(a0.x), f2tf(a1.x), f2tf(a0.y), f2tf(a1.y)};
        uint4 ahi = {f2tf(a0.z), f2tf(a1.z), f2tf(a0.w), f2tf(a1.w)};
        *(uint4*)&As[buf][am][ak + 0] = alo;
        *(uint4*)&As[buf][am][ak + 4] = ahi;
    };
    auto issueB = [&](int s, int buf) {
        #pragma unroll
        for (int cc = 0; cc < CH; cc++) {
            int cid = tid * CH + cc;
            int br = cid >> 2;
            int bc = (cid & 3) << 2;
            unsigned dst = smem_u32(&Bs[buf][br][bc]);
            const float* src = W + (((size_t)s * NN + bn + br) << 4) + bc;
            CP_ASYNC16(dst, src);
        }
        CP_COMMIT();
    };

    fetchA(0);
    issueB(0, 0);
    stageA(0);
    CP_WAIT0();
    __syncthreads();

    int buf = 0;
    #pragma unroll 1
    for (int k0 = 0; k0 < KK; k0 += 16) {
        bool has_next = (k0 + 16 < KK);
        if (has_next) {
            fetchA(k0 + 16);
            issueB((k0 >> 4) + 1, buf ^ 1);
        }

        #pragma unroll
        for (int kk = 0; kk < 2; kk++) {
            int kb = kk * 8;
            unsigned af[2][4];
            #pragma unroll
            for (int mt = 0; mt < 2; mt++) {
                int r0 = wm * 32 + mt * 16;
                uint2 lo = *(const uint2*)&As[buf][r0 + g][kb + 2 * tg];
                uint2 hi = *(const uint2*)&As[buf][r0 + g + 8][kb + 2 * tg];
                af[mt][0] = lo.x; af[mt][1] = hi.x;
                af[mt][2] = lo.y; af[mt][3] = hi.y;
            }
            #pragma unroll
            for (int nt = 0; nt < NT; nt++) {
                int cb = wn * WN + nt * 8 + g;
                uint2 pb = *(const uint2*)&Bs[buf][cb][kb + 2 * tg];
                mma_tf32(acc[0][nt], af[0], pb.x, pb.y);
                mma_tf32(acc[1][nt], af[1], pb.x, pb.y);
            }
        }

        if (has_next) {
            stageA(buf ^ 1);
            CP_WAIT0();
            __syncthreads();
            buf ^= 1;
        }
    }

    #pragma unroll
    for (int mt = 0; mt < 2; mt++) {
        int row0 = bm + wm * 32 + mt * 16 + g;
        #pragma unroll
        for (int nt = 0; nt < NT; nt++) {
            int col = bn + wn * WN + nt * 8 + 2 * tg;
            float bi0 = bias[col], bi1 = bias[col + 1];
            float v0 = acc[mt][nt][0] + bi0;
            float v1 = acc[mt][nt][1] + bi1;
            float v2 = acc[mt][nt][2] + bi0;
            float v3 = acc[mt][nt][3] + bi1;
            if (ACT == 1) {
                v0 = (v0 > 0.f) ? (v0 + 1.f) : expf(v0);
                v1 = (v1 > 0.f) ? (v1 + 1.f) : expf(v1);
                v2 = (v2 > 0.f) ? (v2 + 1.f) : expf(v2);
                v3 = (v3 > 0.f) ? (v3 + 1.f) : expf(v3);
            }
            if (ACT == 2) {
                v0 = fmaxf(v0, 0.f); v1 = fmaxf(v1, 0.f);
                v2 = fmaxf(v2, 0.f); v3 = fmaxf(v3, 0.f);
            }
            float2 p0 = {v0, v1}, p1 = {v2, v3};
            if (OUTMODE == 0) {
                *(float2*)&C[(size_t)row0 * NN + col] = p0;
                *(float2*)&C[(size_t)(row0 + 8) * NN + col] = p1;
            } else {
                int t0 = row0 >> 5, b0i = row0 & 31;
                int t1 = (row0 + 8) >> 5, b1i = (row0 + 8) & 31;
                *(float2*)&C[((size_t)b0i * T_LEN + t0) * NC + col] = p0;
                *(float2*)&C[((size_t)b1i * T_LEN + t1) * NC + col] = p1;
            }
        }
    }
}

// ---------------- residual add + LayerNorm (in place on h) ----------------
__global__ void __launch_bounds__(128)
ln_kernel(float* __restrict__ h, const float* __restrict__ addv,
          const float* __restrict__ g, const float* __restrict__ be)
{
    int row = blockIdx.x, tid = threadIdx.x;
    size_t base = (size_t)row * DM + (tid << 2);
    float4 hv = *(const float4*)&h[base];
    float4 av = *(const float4*)&addv[base];
    float x0 = hv.x + av.x, x1 = hv.y + av.y, x2 = hv.z + av.z, x3 = hv.w + av.w;

    __shared__ float red[4];
    int wid = tid >> 5, lane = tid & 31;

    float s = x0 + x1 + x2 + x3;
    #pragma unroll
    for (int o = 16; o > 0; o >>= 1) s += __shfl_xor_sync(0xffffffffu, s, o);
    if (lane == 0) red[wid] = s;
    __syncthreads();
    float mean = (red[0] + red[1] + red[2] + red[3]) * (1.0f / DM);

    float d0 = x0 - mean, d1 = x1 - mean, d2 = x2 - mean, d3 = x3 - mean;
    float vs = d0 * d0 + d1 * d1 + d2 * d2 + d3 * d3;
    #pragma unroll
    for (int o = 16; o > 0; o >>= 1) vs += __shfl_xor_sync(0xffffffffu, vs, o);
    __syncthreads();
    if (lane == 0) red[wid] = vs;
    __syncthreads();
    float var = (red[0] + red[1] + red[2] + red[3]) * (1.0f / DM);
    float inv = 1.0f / sqrtf(var + EPS_LN);

    int d = tid << 2;
    float4 gv = *(const float4*)&g[d];
    float4 bv = *(const float4*)&be[d];
    float4 o;
    o.x = d0 * inv * gv.x + bv.x;
    o.y = d1 * inv * gv.y + bv.y;
    o.z = d2 * inv * gv.z + bv.z;
    o.w = d3 * inv * gv.w + bv.w;
    *(float4*)&h[base] = o;
}

// ---------------- FUSED attention, conflict-free thread map ----------------
// Block per (b,h); 256 threads: i = tid&63 (row / state-d), sub = tid>>6 (16-col block).
// Warp = 32 consecutive i  ->  k/v/S/Z reads broadcast; q in regs; asb stride 65;
// tile strides 68 (LDS.128 at lane-varying i: banks 4i distinct per 8-lane phase).
__global__ void __launch_bounds__(256, 2)
fused_attn_kernel(const float* __restrict__ Q_, const float* __restrict__ K_,
                  const float* __restrict__ V_, float* __restrict__ O_)
{
    extern __shared__ float sm[];
    float* S   = sm;                    // [64][68]
    float* qs  = sm + 64 * 68;
    float* ks  = qs + 64 * 68;
    float* vsm = ks + 64 * 68;
    float* asb = vsm + 64 * 68;         // [64][65]
    float* Zs  = asb + 64 * 65;         // [64]

    int bh = blockIdx.x;
    int b = bh >> 3, hh = bh & 7;
    int tid = threadIdx.x;
    int i   = tid & 63;
    int sub = tid >> 6;
    int mb  = sub << 4;

    for (int idx = tid; idx < 64 * 68; idx += 256) S[idx] = 0.f;
    if (tid < 64) Zs[tid] = 0.f;

    for (int c = 0; c < NCH; c++) {
        __syncthreads();   // prev-iter readers done before tile overwrite; S/Z init visible

        for (int idx = tid * 4; idx < CHK * DH; idx += 1024) {
            int t = idx >> 6, d = idx & 63;
            size_t gidx = ((size_t)(c * CHK + t) * B_SZ + b) * DM + hh * DH + d;
            int sa = t * 68 + d;
            *(float4*)&qs[sa]  = *(const float4*)&Q_[gidx];
            *(float4*)&ks[sa]  = *(const float4*)&K_[gidx];
            *(float4*)&vsm[sa] = *(const float4*)&V_[gidx];
        }
        __syncthreads();

        // q row -> registers (16 clean LDS.128)
        float4 qreg[16];
        #pragma unroll
        for (int d4 = 0; d4 < 16; d4++) qreg[d4] = *(const float4*)&qs[i * 68 + 4 * d4];

        // phase 1: A[i][mb..mb+15] (k rows broadcast across warp)
        #pragma unroll 2
        for (int jj = 0; jj < 16; jj++) {
            int j = mb + jj;
            const float* kp = &ks[j * 68];
            float a = 0.f;
            #pragma unroll
            for (int d4 = 0; d4 < 16; d4++) {
                float4 kv = *(const float4*)&kp[4 * d4];
                float4 q4 = qreg[d4];
                a += q4.x * kv.x + q4.y * kv.y + q4.z * kv.z + q4.w * kv.w;
            }
            asb[i * 65 + j] = a;
        }

        // old state: acc = q.S_old (cols mb..), den = eps + q.Z_old  (broadcast reads)
        float acc[16] = {};
        float den = EPS_ATTN;
        #pragma unroll
        for (int d4 = 0; d4 < 16; d4++) {
            float4 q4 = qreg[d4];
            #pragma unroll
            for (int e = 0; e < 4; e++) {
                int d = 4 * d4 + e;
                float qd = (e == 0) ? q4.x : (e == 1) ? q4.y : (e == 2) ? q4.z : q4.w;
                den += qd * Zs[d];
                const float* sp = &S[d * 68 + mb];
                #pragma unroll
                for (int m = 0; m < 16; m += 4) {
                    float4 sv = *(const float4*)&sp[m];
                    acc[m + 0] += qd * sv.x;
                    acc[m + 1] += qd * sv.y;
                    acc[m + 2] += qd * sv.z;
                    acc[m + 3] += qd * sv.w;
                }
            }
        }
        __syncthreads();   // all of asb written; all S_old reads complete

        // phase 2a: causal intra-chunk A.V + rowsum
        float rsum = 0.f;
        for (int j = 0; j <= i; j++) {
            float a = asb[i * 65 + j];
            rsum += a;
            const float* vp = &vsm[j * 68 + mb];
            #pragma unroll
            for (int m = 0; m < 16; m += 4) {
                float4 vv = *(const float4*)&vp[m];
                acc[m + 0] += a * vv.x;
                acc[m + 1] += a * vv.y;
                acc[m + 2] += a * vv.z;
                acc[m + 3] += a * vv.w;
            }
        }
        den += rsum;

        float inv = 1.f / den;
        size_t ob = ((size_t)(c * CHK + i) * B_SZ + b) * DM + hh * DH + mb;
        #pragma unroll
        for (int m = 0; m < 16; m += 4) {
            float4 o = {acc[m] * inv, acc[m + 1] * inv, acc[m + 2] * inv, acc[m + 3] * inv};
            *(float4*)&O_[ob + m] = o;
        }

        // phase 2b: state update; thread owns S[d=i][mb..mb+15]
        float up[16] = {};
        float zup = 0.f;
        for (int t = 0; t < CHK; t++) {
            float kd = ks[t * 68 + i];          // lanes consecutive -> conflict-free
            zup += kd;
            const float* vp = &vsm[t * 68 + mb];
            #pragma unroll
            for (int m = 0; m < 16; m += 4) {
                float4 vv = *(const float4*)&vp[m];
                up[m + 0] += kd * vv.x;
                up[m + 1] += kd * vv.y;
                up[m + 2] += kd * vv.z;
                up[m + 3] += kd * vv.w;
            }
        }
        float* srow = &S[i * 68 + mb];
        #pragma unroll
        for (int m = 0; m < 16; m += 4) {
            float4 sv = *(const float4*)&srow[m];
            sv.x += up[m + 0]; sv.y += up[m + 1];
            sv.z += up[m + 2]; sv.w += up[m + 3];
            *(float4*)&srow[m] = sv;
        }
        if (sub == 0) Zs[i] += zup;
    }
}

#define ATT_SMEM ((4 * 64 * 68 + 64 * 65 + 64) * (int)sizeof(float))   // 86528 B

// ---------------- host orchestration ----------------
extern "C" void kernel_launch(void* const* d_in, const int* in_sizes, int n_in,
                              void* d_out, int out_size)
{
    const int*   x   = (const int*)  d_in[0];
    const float* E   = (const float*)d_in[1];
    const float* Wq  = (const float*)d_in[2];
    const float* bq  = (const float*)d_in[3];
    const float* Wk  = (const float*)d_in[4];
    const float* bk  = (const float*)d_in[5];
    const float* Wv  = (const float*)d_in[6];
    const float* bv  = (const float*)d_in[7];
    const float* Wo  = (const float*)d_in[8];
    const float* bo  = (const float*)d_in[9];
    const float* g1  = (const float*)d_in[10];
    const float* be1 = (const float*)d_in[11];
    const float* W1  = (const float*)d_in[12];
    const float* b1  = (const float*)d_in[13];
    const float* W2  = (const float*)d_in[14];
    const float* b2  = (const float*)d_in[15];
    const float* g2  = (const float*)d_in[16];
    const float* be2 = (const float*)d_in[17];
    const float* Wp  = (const float*)d_in[18];
    const float* bp  = (const float*)d_in[19];
    float* out = (float*)d_out;

    float *ph, *pq, *pk, *pv, *pattn, *pff, *pw;
    cudaGetSymbolAddress((void**)&ph,    g_h);
    cudaGetSymbolAddress((void**)&pq,    g_q);
    cudaGetSymbolAddress((void**)&pk,    g_k);
    cudaGetSymbolAddress((void**)&pv,    g_v);
    cudaGetSymbolAddress((void**)&pattn, g_attn);
    cudaGetSymbolAddress((void**)&pff,   g_ff);
    cudaGetSymbolAddress((void**)&pw,    g_wtf);

    static bool attr_done = false;
    if (!attr_done) {
        cudaFuncSetAttribute(fused_attn_kernel,
                             cudaFuncAttributeMaxDynamicSharedMemorySize, ATT_SMEM);
        attr_done = true;
    }

    // weight prep: tf32 round + slab permutation into cp.async-ready image
    {
        auto prep = [&](const float* src, float* dst, int N, int K) {
            int tot = (K >> 4) * N;
            prep_w_kernel<<<(tot + 255) / 256, 256>>>(src, dst, N, K);
        };
        for (int l = 0; l < NL; l++) {
            prep(Wq + (size_t)l * DM * DM,  pw + WOFF_Q + (size_t)l * DM * DM,  DM,  DM);
            prep(Wk + (size_t)l * DM * DM,  pw + WOFF_K + (size_t)l * DM * DM,  DM,  DM);
            prep(Wv + (size_t)l * DM * DM,  pw + WOFF_V + (size_t)l * DM * DM,  DM,  DM);
            prep(Wo + (size_t)l * DM * DM,  pw + WOFF_O + (size_t)l * DM * DM,  DM,  DM);
            prep(W1 + (size_t)l * DM * DFF, pw + WOFF_1 + (size_t)l * DM * DFF, DFF, DM);
            prep(W2 + (size_t)l * DFF * DM, pw + WOFF_2 + (size_t)l * DFF * DM, DM,  DFF);
        }
        prep(Wp, pw + WOFF_P, NC, DM);
    }

    embed_kernel<<<(MROWS * DM) / 256, 256>>>(x, E);

    dim3 gDM(DM / 128, MROWS / 128);    // (4, 512)
    dim3 gFF(DFF / 128, MROWS / 128);   // (16, 512)

    for (int l = 0; l < NL; l++) {
        const float* wq = pw + WOFF_Q + (size_t)l * DM * DM;
        const float* wk = pw + WOFF_K + (size_t)l * DM * DM;
        const float* wv = pw + WOFF_V + (size_t)l * DM * DM;
        const float* wo = pw + WOFF_O + (size_t)l * DM * DM;
        const float* w1 = pw + WOFF_1 + (size_t)l * DM * DFF;
        const float* w2 = pw + WOFF_2 + (size_t)l * DFF * DM;

        mma_gemm_kernel<128, 1, 0, DM, DM><<<gDM, 256>>>(ph, wq, bq + l * DM, pq);
        mma_gemm_kernel<128, 1, 0, DM, DM><<<gDM, 256>>>(ph, wk, bk + l * DM, pk);
        mma_gemm_kernel<128, 0, 0, DM, DM><<<gDM, 256>>>(ph, wv, bv + l * DM, pv);

        fused_attn_kernel<<<B_SZ * NH, 256, ATT_SMEM>>>(pq, pk, pv, pattn);

        mma_gemm_kernel<128, 0, 0, DM, DM><<<gDM, 256>>>(pattn, wo, bo + l * DM, pq);
        ln_kernel<<<MROWS, 128>>>(ph, pq, g1 + l * DM, be1 + l * DM);

        mma_gemm_kernel<128, 2, 0, DFF, DM><<<gFF, 256>>>(ph, w1, b1 + l * DFF, pff);
        mma_gemm_kernel<128, 0, 0, DM, DFF><<<gDM, 256>>>(pff, w2, b2 + l * DM, pq);
        ln_kernel<<<MROWS, 128>>>(ph, pq, g2 + l * DM, be2 + l * DM);
    }

    dim3 gOut(1, MROWS / 128);
    mma_gemm_kernel<64, 0, 1, NC, DM><<<gOut, 256>>>(ph, pw + WOFF_P, bp, out);
}

// round 13
// speedup vs baseline: 3.5048x; 1.1822x over previous
#include <cuda_runtime.h>
#include <math.h>

#define T_LEN 2048
#define B_SZ  32
#define DM    512
#define NH    8
#define DH    64
#define DFF   2048
#define NC    64
#define EV    256
#define NL    2
#define CHK   64
#define NCH   (T_LEN / CHK)          // 32
#define MROWS (T_LEN * B_SZ)         // 65536
#define EPS_ATTN 1e-6f
#define EPS_LN   1e-5f

// ---------------- scratch (device globals; no allocations allowed) ----------------
__device__ float g_h[MROWS * DM];
__device__ float g_q[MROWS * DM];
__device__ float g_k[MROWS * DM];
__device__ float g_v[MROWS * DM];
__device__ float g_attn[MROWS * DM];
__device__ float g_ff[MROWS * DFF];
__device__ float g_wtf[7 * 1024 * 1024];    // tf32-rounded, slab-permuted weights

#define WOFF_Q  0
#define WOFF_K  (2 * DM * DM)
#define WOFF_V  (4 * DM * DM)
#define WOFF_O  (6 * DM * DM)
#define WOFF_1  (8 * DM * DM)
#define WOFF_2  (WOFF_1 + 2 * DM * DFF)
#define WOFF_P  (WOFF_2 + 2 * DM * DFF)

// ---------------- embedding + positional encoding ----------------
__global__ void embed_kernel(const int* __restrict__ x, const float* __restrict__ E) {
    int idx = blockIdx.x * blockDim.x + threadIdx.x;
    int d  = idx & (DM - 1);
    int tb = idx >> 9;
    int b  = tb & (B_SZ - 1);
    int t  = tb >> 5;
    float val;
    if (d < EV) {
        val = E[(size_t)x[t * B_SZ + b] * EV + d];
    } else {
        int j = d - EV;
        float freq = expf((float)(j & ~1) * (-9.210340371976184f / 256.0f));
        float ang = (float)t * freq;
        val = (j & 1) ? cosf(ang) : sinf(ang);
    }
    g_h[idx] = val;
}

// ---------------- tf32 + cp.async helpers ----------------
__device__ __forceinline__ unsigned f2tf(float f) {
    unsigned r;
    asm("cvt.rna.tf32.f32 %0, %1;" : "=r"(r) : "f"(f));
    return r;
}

__device__ __forceinline__ void mma_tf32(float* c, const unsigned* a, unsigned b0, unsigned b1) {
    asm volatile(
        "mma.sync.aligned.m16n8k8.row.col.f32.tf32.tf32.f32 "
        "{%0,%1,%2,%3}, {%4,%5,%6,%7}, {%8,%9}, {%0,%1,%2,%3};"
        : "+f"(c[0]), "+f"(c[1]), "+f"(c[2]), "+f"(c[3])
        : "r"(a[0]), "r"(a[1]), "r"(a[2]), "r"(a[3]), "r"(b0), "r"(b1));
}

__device__ __forceinline__ unsigned smem_u32(const void* p) {
    return (unsigned)__cvta_generic_to_shared(p);
}
#define CP_ASYNC16(dst, src) \
    asm volatile("cp.async.ca.shared.global [%0], [%1], 16;" :: "r"(dst), "l"(src))
#define CP_COMMIT() asm volatile("cp.async.commit_group;")

// ---------------- weight prep: tf32-round + slab-permute into smem image layout ----------
// dst[(s*N + n)*16 + w] = tf32( src[(16s + lk(w))*N + n] ),  lk(w) = ((w&7)>>1)+((w&1)<<2)+(w&8)
__global__ void prep_w_kernel(const float* __restrict__ src, float* __restrict__ dst,
                              int N, int K) {
    int idx = blockIdx.x * blockDim.x + threadIdx.x;
    int total = (K >> 4) * N;
    if (idx >= total) return;
    int n = idx % N;
    int s = idx / N;
    const float* sp = src + ((size_t)(s << 4)) * N + n;
    float o[16];
    #pragma unroll
    for (int w = 0; w < 16; w++) {
        int lk = ((w & 7) >> 1) + ((w & 1) << 2) + (w & 8);
        o[w] = __uint_as_float(f2tf(sp[(size_t)lk * N]));
    }
    float* dp = dst + ((size_t)idx << 4);
    #pragma unroll
    for (int v = 0; v < 4; v++)
        *(float4*)&dp[4 * v] = make_float4(o[4*v], o[4*v+1], o[4*v+2], o[4*v+3]);
}

// ---------------- fully-async tf32 GEMM: C = act(A[M,K] @ W[K,N] + bias) ----------------
// Block 128 x BN, 256 threads = 8 warps (4M x 2N), warp tile 32 x BN/2.
// 3-stage cp.async pipeline, both operands async:
//   A: raw fp32 chunks -> As[m][16] (stride 20; banks (20g+tg)%32 all-distinct -> clean LDS.32)
//      mma consumes raw fp32 bits as tf32 (HW ignores low mantissa bits).
//   B: pre-rounded+permuted image -> Bs[n][16] (stride 24; LDS.64 pairs, proven clean).
template<int BN, int ACT, int OUTMODE, int NN, int KK>
__global__ void __launch_bounds__(256, 2)
mma_gemm_kernel(const float* __restrict__ A, const float* __restrict__ W,
                const float* __restrict__ bias, float* __restrict__ C)
{
    constexpr int NT = BN / 16;
    constexpr int WN = BN / 2;
    constexpr int BCH = BN / 64;              // B cp.async chunks per thread per slab
    constexpr int ASTR = 20;                  // A smem row stride (words)
    constexpr int AWORDS = 128 * ASTR;        // 2560
    constexpr int STAGE = AWORDS + BN * 24;   // words per stage
    constexpr int NS = KK / 16;               // slabs

    extern __shared__ float smp[];

    int tid = threadIdx.x;
    int bn = blockIdx.x * BN;
    int bm = blockIdx.y * 128;

    int wid = tid >> 5, lane = tid & 31;
    int wm = wid >> 1, wn = wid & 1;
    int g = lane >> 2, tg = lane & 3;

    float acc[2][NT][4] = {};

    auto issue = [&](int s, int st) {
        float* As = smp + st * STAGE;
        float* Bsb = smp + st * STAGE + AWORDS;
        // A: 512 chunks of 16B (128 rows x 4), 2 per thread
        #pragma unroll
        for (int cc = 0; cc < 2; cc++) {
            int cid = tid + cc * 256;
            int m = cid >> 2;
            int c4 = (cid & 3) << 2;
            unsigned dst = smem_u32(&As[m * ASTR + c4]);
            const float* src = A + (size_t)(bm + m) * KK + (s << 4) + c4;
            CP_ASYNC16(dst, src);
        }
        // B: BN*4 chunks, contiguous image -> perfectly coalesced
        #pragma unroll
        for (int cc = 0; cc < BCH; cc++) {
            int cid = tid + cc * 256;
            int br = cid >> 2;
            int bc = (cid & 3) << 2;
            unsigned dst = smem_u32(&Bsb[br * 24 + bc]);
            const float* src = W + (((size_t)s * NN + bn + br) << 4) + bc;
            CP_ASYNC16(dst, src);
        }
    };

    issue(0, 0); CP_COMMIT();
    if (NS > 1) issue(1, 1);
    CP_COMMIT();

    int st = 0;
    #pragma unroll 1
    for (int s = 0; s < NS; s++) {
        asm volatile("cp.async.wait_group 1;");
        __syncthreads();

        const unsigned* Abuf = (const unsigned*)(smp + st * STAGE);
        const unsigned* Bbuf = (const unsigned*)(smp + st * STAGE + AWORDS);

        #pragma unroll
        for (int kk = 0; kk < 2; kk++) {
            int kb = kk * 8;
            unsigned af[2][4];
            #pragma unroll
            for (int mt = 0; mt < 2; mt++) {
                int r0 = wm * 32 + mt * 16;
                af[mt][0] = Abuf[(r0 + g)     * ASTR + kb + tg];
                af[mt][1] = Abuf[(r0 + g + 8) * ASTR + kb + tg];
                af[mt][2] = Abuf[(r0 + g)     * ASTR + kb + tg + 4];
                af[mt][3] = Abuf[(r0 + g + 8) * ASTR + kb + tg + 4];
            }
            #pragma unroll
            for (int nt = 0; nt < NT; nt++) {
                int cb = wn * WN + nt * 8 + g;
                uint2 pb = *(const uint2*)&Bbuf[cb * 24 + kb + 2 * tg];
                mma_tf32(acc[0][nt], af[0], pb.x, pb.y);
                mma_tf32(acc[1][nt], af[1], pb.x, pb.y);
            }
        }

        int sn = s + 2;
        if (sn < NS) issue(sn, (st + 2) % 3);
        CP_COMMIT();
        st = (st + 1) % 3;
    }

    #pragma unroll
    for (int mt = 0; mt < 2; mt++) {
        int row0 = bm + wm * 32 + mt * 16 + g;
        #pragma unroll
        for (int nt = 0; nt < NT; nt++) {
            int col = bn + wn * WN + nt * 8 + 2 * tg;
            float bi0 = bias[col], bi1 = bias[col + 1];
            float v0 = acc[mt][nt][0] + bi0;
            float v1 = acc[mt][nt][1] + bi1;
            float v2 = acc[mt][nt][2] + bi0;
            float v3 = acc[mt][nt][3] + bi1;
            if (ACT == 1) {
                v0 = (v0 > 0.f) ? (v0 + 1.f) : expf(v0);
                v1 = (v1 > 0.f) ? (v1 + 1.f) : expf(v1);
                v2 = (v2 > 0.f) ? (v2 + 1.f) : expf(v2);
                v3 = (v3 > 0.f) ? (v3 + 1.f) : expf(v3);
            }
            if (ACT == 2) {
                v0 = fmaxf(v0, 0.f); v1 = fmaxf(v1, 0.f);
                v2 = fmaxf(v2, 0.f); v3 = fmaxf(v3, 0.f);
            }
            float2 p0 = {v0, v1}, p1 = {v2, v3};
            if (OUTMODE == 0) {
                *(float2*)&C[(size_t)row0 * NN + col] = p0;
                *(float2*)&C[(size_t)(row0 + 8) * NN + col] = p1;
            } else {
                int t0 = row0 >> 5, b0i = row0 & 31;
                int t1 = (row0 + 8) >> 5, b1i = (row0 + 8) & 31;
                *(float2*)&C[((size_t)b0i * T_LEN + t0) * NC + col] = p0;
                *(float2*)&C[((size_t)b1i * T_LEN + t1) * NC + col] = p1;
            }
        }
    }
}

#define GEMM_SMEM(BN) (3 * (128 * 20 + (BN) * 24) * (int)sizeof(float))

// ---------------- residual add + LayerNorm (in place on h) ----------------
__global__ void __launch_bounds__(128)
ln_kernel(float* __restrict__ h, const float* __restrict__ addv,
          const float* __restrict__ g, const float* __restrict__ be)
{
    int row = blockIdx.x, tid = threadIdx.x;
    size_t base = (size_t)row * DM + (tid << 2);
    float4 hv = *(const float4*)&h[base];
    float4 av = *(const float4*)&addv[base];
    float x0 = hv.x + av.x, x1 = hv.y + av.y, x2 = hv.z + av.z, x3 = hv.w + av.w;

    __shared__ float red[4];
    int wid = tid >> 5, lane = tid & 31;

    float s = x0 + x1 + x2 + x3;
    #pragma unroll
    for (int o = 16; o > 0; o >>= 1) s += __shfl_xor_sync(0xffffffffu, s, o);
    if (lane == 0) red[wid] = s;
    __syncthreads();
    float mean = (red[0] + red[1] + red[2] + red[3]) * (1.0f / DM);

    float d0 = x0 - mean, d1 = x1 - mean, d2 = x2 - mean, d3 = x3 - mean;
    float vs = d0 * d0 + d1 * d1 + d2 * d2 + d3 * d3;
    #pragma unroll
    for (int o = 16; o > 0; o >>= 1) vs += __shfl_xor_sync(0xffffffffu, vs, o);
    __syncthreads();
    if (lane == 0) red[wid] = vs;
    __syncthreads();
    float var = (red[0] + red[1] + red[2] + red[3]) * (1.0f / DM);
    float inv = 1.0f / sqrtf(var + EPS_LN);

    int d = tid << 2;
    float4 gv = *(const float4*)&g[d];
    float4 bv = *(const float4*)&be[d];
    float4 o;
    o.x = d0 * inv * gv.x + bv.x;
    o.y = d1 * inv * gv.y + bv.y;
    o.z = d2 * inv * gv.z + bv.z;
    o.w = d3 * inv * gv.w + bv.w;
    *(float4*)&h[base] = o;
}

// ---------------- FUSED attention, conflict-free thread map ----------------
__global__ void __launch_bounds__(256, 2)
fused_attn_kernel(const float* __restrict__ Q_, const float* __restrict__ K_,
                  const float* __restrict__ V_, float* __restrict__ O_)
{
    extern __shared__ float sm[];
    float* S   = sm;                    // [64][68]
    float* qs  = sm + 64 * 68;
    float* ks  = qs + 64 * 68;
    float* vsm = ks + 64 * 68;
    float* asb = vsm + 64 * 68;         // [64][65]
    float* Zs  = asb + 64 * 65;         // [64]

    int bh = blockIdx.x;
    int b = bh >> 3, hh = bh & 7;
    int tid = threadIdx.x;
    int i   = tid & 63;
    int sub = tid >> 6;
    int mb  = sub << 4;

    for (int idx = tid; idx < 64 * 68; idx += 256) S[idx] = 0.f;
    if (tid < 64) Zs[tid] = 0.f;

    for (int c = 0; c < NCH; c++) {
        __syncthreads();

        for (int idx = tid * 4; idx < CHK * DH; idx += 1024) {
            int t = idx >> 6, d = idx & 63;
            size_t gidx = ((size_t)(c * CHK + t) * B_SZ + b) * DM + hh * DH + d;
            int sa = t * 68 + d;
            *(float4*)&qs[sa]  = *(const float4*)&Q_[gidx];
            *(float4*)&ks[sa]  = *(const float4*)&K_[gidx];
            *(float4*)&vsm[sa] = *(const float4*)&V_[gidx];
        }
        __syncthreads();

        float4 qreg[16];
        #pragma unroll
        for (int d4 = 0; d4 < 16; d4++) qreg[d4] = *(const float4*)&qs[i * 68 + 4 * d4];

        #pragma unroll 2
        for (int jj = 0; jj < 16; jj++) {
            int j = mb + jj;
            const float* kp = &ks[j * 68];
            float a = 0.f;
            #pragma unroll
            for (int d4 = 0; d4 < 16; d4++) {
                float4 kv = *(const float4*)&kp[4 * d4];
                float4 q4 = qreg[d4];
                a += q4.x * kv.x + q4.y * kv.y + q4.z * kv.z + q4.w * kv.w;
            }
            asb[i * 65 + j] = a;
        }

        float acc[16] = {};
        float den = EPS_ATTN;
        #pragma unroll
        for (int d4 = 0; d4 < 16; d4++) {
            float4 q4 = qreg[d4];
            #pragma unroll
            for (int e = 0; e < 4; e++) {
                int d = 4 * d4 + e;
                float qd = (e == 0) ? q4.x : (e == 1) ? q4.y : (e == 2) ? q4.z : q4.w;
                den += qd * Zs[d];
                const float* sp = &S[d * 68 + mb];
                #pragma unroll
                for (int m = 0; m < 16; m += 4) {
                    float4 sv = *(const float4*)&sp[m];
                    acc[m + 0] += qd * sv.x;
                    acc[m + 1] += qd * sv.y;
                    acc[m + 2] += qd * sv.z;
                    acc[m + 3] += qd * sv.w;
                }
            }
        }
        __syncthreads();

        float rsum = 0.f;
        for (int j = 0; j <= i; j++) {
            float a = asb[i * 65 + j];
            rsum += a;
            const float* vp = &vsm[j * 68 + mb];
            #pragma unroll
            for (int m = 0; m < 16; m += 4) {
                float4 vv = *(const float4*)&vp[m];
                acc[m + 0] += a * vv.x;
                acc[m + 1] += a * vv.y;
                acc[m + 2] += a * vv.z;
                acc[m + 3] += a * vv.w;
            }
        }
        den += rsum;

        float inv = 1.f / den;
        size_t ob = ((size_t)(c * CHK + i) * B_SZ + b) * DM + hh * DH + mb;
        #pragma unroll
        for (int m = 0; m < 16; m += 4) {
            float4 o = {acc[m] * inv, acc[m + 1] * inv, acc[m + 2] * inv, acc[m + 3] * inv};
            *(float4*)&O_[ob + m] = o;
        }

        float up[16] = {};
        float zup = 0.f;
        for (int t = 0; t < CHK; t++) {
            float kd = ks[t * 68 + i];
            zup += kd;
            const float* vp = &vsm[t * 68 + mb];
            #pragma unroll
            for (int m = 0; m < 16; m += 4) {
                float4 vv = *(const float4*)&vp[m];
                up[m + 0] += kd * vv.x;
                up[m + 1] += kd * vv.y;
                up[m + 2] += kd * vv.z;
                up[m + 3] += kd * vv.w;
            }
        }
        float* srow = &S[i * 68 + mb];
        #pragma unroll
        for (int m = 0; m < 16; m += 4) {
            float4 sv = *(const float4*)&srow[m];
            sv.x += up[m + 0]; sv.y += up[m + 1];
            sv.z += up[m + 2]; sv.w += up[m + 3];
            *(float4*)&srow[m] = sv;
        }
        if (sub == 0) Zs[i] += zup;
    }
}

#define ATT_SMEM ((4 * 64 * 68 + 64 * 65 + 64) * (int)sizeof(float))   // 86528 B

// ---------------- host orchestration ----------------
extern "C" void kernel_launch(void* const* d_in, const int* in_sizes, int n_in,
                              void* d_out, int out_size)
{
    const int*   x   = (const int*)  d_in[0];
    const float* E   = (const float*)d_in[1];
    const float* Wq  = (const float*)d_in[2];
    const float* bq  = (const float*)d_in[3];
    const float* Wk  = (const float*)d_in[4];
    const float* bk  = (const float*)d_in[5];
    const float* Wv  = (const float*)d_in[6];
    const float* bv  = (const float*)d_in[7];
    const float* Wo  = (const float*)d_in[8];
    const float* bo  = (const float*)d_in[9];
    const float* g1  = (const float*)d_in[10];
    const float* be1 = (const float*)d_in[11];
    const float* W1  = (const float*)d_in[12];
    const float* b1  = (const float*)d_in[13];
    const float* W2  = (const float*)d_in[14];
    const float* b2  = (const float*)d_in[15];
    const float* g2  = (const float*)d_in[16];
    const float* be2 = (const float*)d_in[17];
    const float* Wp  = (const float*)d_in[18];
    const float* bp  = (const float*)d_in[19];
    float* out = (float*)d_out;

    float *ph, *pq, *pk, *pv, *pattn, *pff, *pw;
    cudaGetSymbolAddress((void**)&ph,    g_h);
    cudaGetSymbolAddress((void**)&pq,    g_q);
    cudaGetSymbolAddress((void**)&pk,    g_k);
    cudaGetSymbolAddress((void**)&pv,    g_v);
    cudaGetSymbolAddress((void**)&pattn, g_attn);
    cudaGetSymbolAddress((void**)&pff,   g_ff);
    cudaGetSymbolAddress((void**)&pw,    g_wtf);

    static bool attr_done = false;
    if (!attr_done) {
        cudaFuncSetAttribute(fused_attn_kernel,
                             cudaFuncAttributeMaxDynamicSharedMemorySize, ATT_SMEM);
        cudaFuncSetAttribute(mma_gemm_kernel<128, 1, 0, DM, DM>,
                             cudaFuncAttributeMaxDynamicSharedMemorySize, GEMM_SMEM(128));
        cudaFuncSetAttribute(mma_gemm_kernel<128, 0, 0, DM, DM>,
                             cudaFuncAttributeMaxDynamicSharedMemorySize, GEMM_SMEM(128));
        cudaFuncSetAttribute(mma_gemm_kernel<128, 2, 0, DFF, DM>,
                             cudaFuncAttributeMaxDynamicSharedMemorySize, GEMM_SMEM(128));
        cudaFuncSetAttribute(mma_gemm_kernel<128, 0, 0, DM, DFF>,
                             cudaFuncAttributeMaxDynamicSharedMemorySize, GEMM_SMEM(128));
        cudaFuncSetAttribute(mma_gemm_kernel<64, 0, 1, NC, DM>,
                             cudaFuncAttributeMaxDynamicSharedMemorySize, GEMM_SMEM(64));
        attr_done = true;
    }

    // weight prep: tf32 round + slab permutation into cp.async-ready image
    {
        auto prep = [&](const float* src, float* dst, int N, int K) {
            int tot = (K >> 4) * N;
            prep_w_kernel<<<(tot + 255) / 256, 256>>>(src, dst, N, K);
        };
        for (int l = 0; l < NL; l++) {
            prep(Wq + (size_t)l * DM * DM,  pw + WOFF_Q + (size_t)l * DM * DM,  DM,  DM);
            prep(Wk + (size_t)l * DM * DM,  pw + WOFF_K + (size_t)l * DM * DM,  DM,  DM);
            prep(Wv + (size_t)l * DM * DM,  pw + WOFF_V + (size_t)l * DM * DM,  DM,  DM);
            prep(Wo + (size_t)l * DM * DM,  pw + WOFF_O + (size_t)l * DM * DM,  DM,  DM);
            prep(W1 + (size_t)l * DM * DFF, pw + WOFF_1 + (size_t)l * DM * DFF, DFF, DM);
            prep(W2 + (size_t)l * DFF * DM, pw + WOFF_2 + (size_t)l * DFF * DM, DM,  DFF);
        }
        prep(Wp, pw + WOFF_P, NC, DM);
    }

    embed_kernel<<<(MROWS * DM) / 256, 256>>>(x, E);

    dim3 gDM(DM / 128, MROWS / 128);    // (4, 512)
    dim3 gFF(DFF / 128, MROWS / 128);   // (16, 512)

    for (int l = 0; l < NL; l++) {
        const float* wq = pw + WOFF_Q + (size_t)l * DM * DM;
        const float* wk = pw + WOFF_K + (size_t)l * DM * DM;
        const float* wv = pw + WOFF_V + (size_t)l * DM * DM;
        const float* wo = pw + WOFF_O + (size_t)l * DM * DM;
        const float* w1 = pw + WOFF_1 + (size_t)l * DM * DFF;
        const float* w2 = pw + WOFF_2 + (size_t)l * DFF * DM;

        mma_gemm_kernel<128, 1, 0, DM, DM><<<gDM, 256, GEMM_SMEM(128)>>>(ph, wq, bq + l * DM, pq);
        mma_gemm_kernel<128, 1, 0, DM, DM><<<gDM, 256, GEMM_SMEM(128)>>>(ph, wk, bk + l * DM, pk);
        mma_gemm_kernel<128, 0, 0, DM, DM><<<gDM, 256, GEMM_SMEM(128)>>>(ph, wv, bv + l * DM, pv);

        fused_attn_kernel<<<B_SZ * NH, 256, ATT_SMEM>>>(pq, pk, pv, pattn);

        mma_gemm_kernel<128, 0, 0, DM, DM><<<gDM, 256, GEMM_SMEM(128)>>>(pattn, wo, bo + l * DM, pq);
        ln_kernel<<<MROWS, 128>>>(ph, pq, g1 + l * DM, be1 + l * DM);

        mma_gemm_kernel<128, 2, 0, DFF, DM><<<gFF, 256, GEMM_SMEM(128)>>>(ph, w1, b1 + l * DFF, pff);
        mma_gemm_kernel<128, 0, 0, DM, DFF><<<gDM, 256, GEMM_SMEM(128)>>>(pff, w2, b2 + l * DM, pq);
        ln_kernel<<<MROWS, 128>>>(ph, pq, g2 + l * DM, be2 + l * DM);
    }

    dim3 gOut(1, MROWS / 128);
    mma_gemm_kernel<64, 0, 1, NC, DM><<<gOut, 256, GEMM_SMEM(64)>>>(ph, pw + WOFF_P, bp, out);
}